// round 2
// baseline (speedup 1.0000x reference)
#include <cuda_runtime.h>

// Problem constants
#define BATCH 8
#define NSEQ  2048
#define DIM   512
#define ROWS  (BATCH * NSEQ)   // 16384

// GEMM tiling
#define BM 128
#define BN 128
#define BK 32
#define BMP (BM + 4)   // padded smem stride to avoid bank conflicts
#define BNP (BN + 4)
#define NTHREADS 256

// Scratch (allocation-free rule: __device__ globals)
__device__ float g_q[(size_t)ROWS * DIM];
__device__ float g_k[(size_t)ROWS * DIM];
__device__ float g_v[(size_t)ROWS * DIM];
__device__ float g_s[(size_t)BATCH * NSEQ * NSEQ];

// ---------------------------------------------------------------------------
// NT GEMM body: C[m,n] = sum_k A[m,k] * B[n,k] (+ bias[n])
// A, B, C already offset to this block's tile origin.
// ---------------------------------------------------------------------------
__device__ __forceinline__ void gemm_nt_body(
    const float* __restrict__ A, int lda,
    const float* __restrict__ B, int ldb,
    const float* __restrict__ bias,   // may be nullptr; indexed by local col
    float* __restrict__ C, int ldc,
    int K)
{
    __shared__ float As[BK][BMP];
    __shared__ float Bs[BK][BNP];

    const int tid = threadIdx.x;
    const int tm  = tid >> 4;        // 0..15
    const int tn  = tid & 15;        // 0..15
    const int lr  = tid >> 3;        // loader row base 0..31
    const int lc  = (tid & 7) << 2;  // loader k-col 0,4,...,28

    float acc[8][8];
#pragma unroll
    for (int i = 0; i < 8; i++)
#pragma unroll
        for (int j = 0; j < 8; j++) acc[i][j] = 0.f;

    for (int k0 = 0; k0 < K; k0 += BK) {
#pragma unroll
        for (int i = 0; i < 4; i++) {
            int r = lr + i * 32;
            float4 va = *(const float4*)(A + (size_t)r * lda + k0 + lc);
            As[lc + 0][r] = va.x; As[lc + 1][r] = va.y;
            As[lc + 2][r] = va.z; As[lc + 3][r] = va.w;
            float4 vb = *(const float4*)(B + (size_t)r * ldb + k0 + lc);
            Bs[lc + 0][r] = vb.x; Bs[lc + 1][r] = vb.y;
            Bs[lc + 2][r] = vb.z; Bs[lc + 3][r] = vb.w;
        }
        __syncthreads();
#pragma unroll
        for (int kk = 0; kk < BK; kk++) {
            float a[8], b[8];
            *(float4*)&a[0] = *(const float4*)&As[kk][tm * 8];
            *(float4*)&a[4] = *(const float4*)&As[kk][tm * 8 + 4];
            *(float4*)&b[0] = *(const float4*)&Bs[kk][tn * 8];
            *(float4*)&b[4] = *(const float4*)&Bs[kk][tn * 8 + 4];
#pragma unroll
            for (int i = 0; i < 8; i++)
#pragma unroll
                for (int j = 0; j < 8; j++)
                    acc[i][j] = fmaf(a[i], b[j], acc[i][j]);
        }
        __syncthreads();
    }

#pragma unroll
    for (int i = 0; i < 8; i++) {
        int row = tm * 8 + i;
#pragma unroll
        for (int j = 0; j < 8; j += 4) {
            int col = tn * 8 + j;
            float4 o;
            o.x = acc[i][j + 0]; o.y = acc[i][j + 1];
            o.z = acc[i][j + 2]; o.w = acc[i][j + 3];
            if (bias) {
                o.x += bias[col + 0]; o.y += bias[col + 1];
                o.z += bias[col + 2]; o.w += bias[col + 3];
            }
            *(float4*)(C + (size_t)row * ldc + col) = o;
        }
    }
}

// ---------------------------------------------------------------------------
// NN GEMM body: C[m,n] = sum_k A[m,k] * B[k,n]
// ---------------------------------------------------------------------------
__device__ __forceinline__ void gemm_nn_body(
    const float* __restrict__ A, int lda,
    const float* __restrict__ B, int ldb,
    float* __restrict__ C, int ldc,
    int K)
{
    __shared__ float As[BK][BMP];
    __shared__ float Bs[BK][BNP];

    const int tid = threadIdx.x;
    const int tm  = tid >> 4;
    const int tn  = tid & 15;
    const int lr  = tid >> 3;
    const int lc  = (tid & 7) << 2;
    const int br  = tid >> 5;        // 0..7, B loader row base
    const int bc  = (tid & 31) << 2; // 0,4,...,124

    float acc[8][8];
#pragma unroll
    for (int i = 0; i < 8; i++)
#pragma unroll
        for (int j = 0; j < 8; j++) acc[i][j] = 0.f;

    for (int k0 = 0; k0 < K; k0 += BK) {
#pragma unroll
        for (int i = 0; i < 4; i++) {
            int r = lr + i * 32;
            float4 va = *(const float4*)(A + (size_t)r * lda + k0 + lc);
            As[lc + 0][r] = va.x; As[lc + 1][r] = va.y;
            As[lc + 2][r] = va.z; As[lc + 3][r] = va.w;
            int kr = br + i * 8;
            float4 vb = *(const float4*)(B + (size_t)(k0 + kr) * ldb + bc);
            *(float4*)&Bs[kr][bc] = vb;
        }
        __syncthreads();
#pragma unroll
        for (int kk = 0; kk < BK; kk++) {
            float a[8], b[8];
            *(float4*)&a[0] = *(const float4*)&As[kk][tm * 8];
            *(float4*)&a[4] = *(const float4*)&As[kk][tm * 8 + 4];
            *(float4*)&b[0] = *(const float4*)&Bs[kk][tn * 8];
            *(float4*)&b[4] = *(const float4*)&Bs[kk][tn * 8 + 4];
#pragma unroll
            for (int i = 0; i < 8; i++)
#pragma unroll
                for (int j = 0; j < 8; j++)
                    acc[i][j] = fmaf(a[i], b[j], acc[i][j]);
        }
        __syncthreads();
    }

#pragma unroll
    for (int i = 0; i < 8; i++) {
        int row = tm * 8 + i;
#pragma unroll
        for (int j = 0; j < 8; j += 4) {
            int col = tn * 8 + j;
            float4 o;
            o.x = acc[i][j + 0]; o.y = acc[i][j + 1];
            o.z = acc[i][j + 2]; o.w = acc[i][j + 3];
            *(float4*)(C + (size_t)row * ldc + col) = o;
        }
    }
}

// ---------------------------------------------------------------------------
// Kernel 1: fused QKV projections. q/k/v[r,e] = sum_d x[r,d]*W[e,d] + b[e]
// grid = (DIM/BN, ROWS/BM, 3)
// ---------------------------------------------------------------------------
__global__ __launch_bounds__(NTHREADS)
void qkv_kernel(const float* __restrict__ x,
                const float* __restrict__ Wq, const float* __restrict__ bq,
                const float* __restrict__ Wk, const float* __restrict__ bk,
                const float* __restrict__ Wv, const float* __restrict__ bv)
{
    const float* W; const float* bias; float* out;
    if (blockIdx.z == 0)      { W = Wq; bias = bq; out = g_q; }
    else if (blockIdx.z == 1) { W = Wk; bias = bk; out = g_k; }
    else                      { W = Wv; bias = bv; out = g_v; }

    const float* A = x + (size_t)blockIdx.y * BM * DIM;
    const float* B = W + (size_t)blockIdx.x * BN * DIM;
    float*       C = out + (size_t)blockIdx.y * BM * DIM + blockIdx.x * BN;
    gemm_nt_body(A, DIM, B, DIM, bias + blockIdx.x * BN, C, DIM, DIM);
}

// ---------------------------------------------------------------------------
// Kernel 2: S[b] = Q[b] @ K[b]^T.  grid = (NSEQ/BN, NSEQ/BM, BATCH)
// ---------------------------------------------------------------------------
__global__ __launch_bounds__(NTHREADS)
void scores_kernel()
{
    int b = blockIdx.z;
    const float* A = g_q + (size_t)b * NSEQ * DIM + (size_t)blockIdx.y * BM * DIM;
    const float* B = g_k + (size_t)b * NSEQ * DIM + (size_t)blockIdx.x * BN * DIM;
    float*       C = g_s + (size_t)b * NSEQ * NSEQ
                         + (size_t)blockIdx.y * BM * NSEQ + blockIdx.x * BN;
    gemm_nt_body(A, DIM, B, DIM, nullptr, C, NSEQ, DIM);
}

// ---------------------------------------------------------------------------
// Kernel 3: stable softmax over each row of S (rows of length NSEQ).
// grid = BATCH*NSEQ blocks, 256 threads, 8 elems/thread.
// ---------------------------------------------------------------------------
__global__ __launch_bounds__(NTHREADS)
void softmax_kernel()
{
    __shared__ float red[8];
    float* S = g_s + (size_t)blockIdx.x * NSEQ;
    const int tid  = threadIdx.x;
    const int lane = tid & 31;
    const int wid  = tid >> 5;

    float4 v0 = *(const float4*)(S + tid * 8);
    float4 v1 = *(const float4*)(S + tid * 8 + 4);
    float e[8] = {v0.x, v0.y, v0.z, v0.w, v1.x, v1.y, v1.z, v1.w};

    // row max
    float m = e[0];
#pragma unroll
    for (int i = 1; i < 8; i++) m = fmaxf(m, e[i]);
#pragma unroll
    for (int off = 16; off > 0; off >>= 1)
        m = fmaxf(m, __shfl_xor_sync(0xffffffffu, m, off));
    if (lane == 0) red[wid] = m;
    __syncthreads();
    float bm = red[0];
#pragma unroll
    for (int i = 1; i < 8; i++) bm = fmaxf(bm, red[i]);
    __syncthreads();

    // exp + sum
    float s = 0.f;
#pragma unroll
    for (int i = 0; i < 8; i++) { e[i] = __expf(e[i] - bm); s += e[i]; }
#pragma unroll
    for (int off = 16; off > 0; off >>= 1)
        s += __shfl_xor_sync(0xffffffffu, s, off);
    if (lane == 0) red[wid] = s;
    __syncthreads();
    float bs = 0.f;
#pragma unroll
    for (int i = 0; i < 8; i++) bs += red[i];

    float inv = 1.0f / bs;
    float4 o0 = make_float4(e[0] * inv, e[1] * inv, e[2] * inv, e[3] * inv);
    float4 o1 = make_float4(e[4] * inv, e[5] * inv, e[6] * inv, e[7] * inv);
    *(float4*)(S + tid * 8)     = o0;
    *(float4*)(S + tid * 8 + 4) = o1;
}

// ---------------------------------------------------------------------------
// Kernel 4: O[b] = P[b] @ V[b].  grid = (DIM/BN, NSEQ/BM, BATCH)
// ---------------------------------------------------------------------------
__global__ __launch_bounds__(NTHREADS)
void out_kernel(float* __restrict__ out)
{
    int b = blockIdx.z;
    const float* A = g_s + (size_t)b * NSEQ * NSEQ + (size_t)blockIdx.y * BM * NSEQ;
    const float* B = g_v + (size_t)b * NSEQ * DIM + blockIdx.x * BN;
    float*       C = out + (size_t)b * NSEQ * DIM
                         + (size_t)blockIdx.y * BM * DIM + blockIdx.x * BN;
    gemm_nn_body(A, NSEQ, B, DIM, C, DIM, NSEQ);
}

// ---------------------------------------------------------------------------
extern "C" void kernel_launch(void* const* d_in, const int* in_sizes, int n_in,
                              void* d_out, int out_size)
{
    const float* x  = (const float*)d_in[0];
    const float* Wq = (const float*)d_in[1];
    const float* bq = (const float*)d_in[2];
    const float* Wk = (const float*)d_in[3];
    const float* bk = (const float*)d_in[4];
    const float* Wv = (const float*)d_in[5];
    const float* bv = (const float*)d_in[6];
    float* out = (float*)d_out;

    dim3 blk(NTHREADS);
    qkv_kernel<<<dim3(DIM / BN, ROWS / BM, 3), blk>>>(x, Wq, bq, Wk, bk, Wv, bv);
    scores_kernel<<<dim3(NSEQ / BN, NSEQ / BM, BATCH), blk>>>();
    softmax_kernel<<<dim3(BATCH * NSEQ), blk>>>();
    out_kernel<<<dim3(DIM / BN, NSEQ / BM, BATCH), blk>>>(out);
}

// round 5
// speedup vs baseline: 1.2510x; 1.2510x over previous
#include <cuda_runtime.h>
#include <cuda_bf16.h>
#include <cstdint>

#define BATCH 8
#define NSEQ  2048
#define DIM   512
#define ROWS  (BATCH * NSEQ)   // 16384

// ---- mma.sync GEMM tiling ----
#define BM 128
#define BN 128
#define BK 32
#define NTHREADS 256
#define ROWB 80                 // smem row stride in bytes (conflict-free, 16B aligned)
#define TILE_SM (128 * ROWB)    // 10240 B per operand buffer

#define XSZ (ROWS * DIM)
#define WSZ (DIM * DIM)
#define SSZ ((size_t)BATCH * NSEQ * NSEQ)

// ---------------------------------------------------------------------------
// Scratch (allocation-free rule: __device__ globals)
// ---------------------------------------------------------------------------
__device__ __nv_bfloat16 g_xh[3][XSZ];
__device__ __nv_bfloat16 g_wqh[3][WSZ];
__device__ __nv_bfloat16 g_wkh[3][WSZ];
__device__ __nv_bfloat16 g_wvh[3][WSZ];
__device__ __nv_bfloat16 g_qh[3][XSZ];
__device__ __nv_bfloat16 g_kh[3][XSZ];
__device__ float         g_v[XSZ];
__device__ __nv_bfloat16 g_vth[2][(size_t)BATCH * DIM * NSEQ];
__device__ float         g_s[SSZ];
__device__ __nv_bfloat16 g_ph[2][SSZ];

// ---------------------------------------------------------------------------
// PTX helpers
// ---------------------------------------------------------------------------
static __device__ __forceinline__ uint32_t smem_u32(const void* p) {
    uint32_t a;
    asm("{ .reg .u64 t; cvta.to.shared.u64 t, %1; cvt.u32.u64 %0, t; }" : "=r"(a) : "l"(p));
    return a;
}
static __device__ __forceinline__ void cp16(uint32_t saddr, const void* g) {
    asm volatile("cp.async.cg.shared.global [%0], [%1], 16;" :: "r"(saddr), "l"(g));
}
static __device__ __forceinline__ void cp_commit() {
    asm volatile("cp.async.commit_group;" ::: "memory");
}
static __device__ __forceinline__ void cp_wait0() {
    asm volatile("cp.async.wait_group 0;" ::: "memory");
}
static __device__ __forceinline__ void cp_wait1() {
    asm volatile("cp.async.wait_group 1;" ::: "memory");
}
#define LDSM4(R0, R1, R2, R3, addr) \
    asm volatile("ldmatrix.sync.aligned.m8n8.x4.shared.b16 {%0,%1,%2,%3}, [%4];" \
                 : "=r"(R0), "=r"(R1), "=r"(R2), "=r"(R3) : "r"(addr))
#define MMA16816(c0, c1, c2, c3, a0, a1, a2, a3, b0, b1) \
    asm volatile("mma.sync.aligned.m16n8k16.row.col.f32.bf16.bf16.f32 " \
                 "{%0,%1,%2,%3}, {%4,%5,%6,%7}, {%8,%9}, {%0,%1,%2,%3};" \
                 : "+f"(c0), "+f"(c1), "+f"(c2), "+f"(c3) \
                 : "r"(a0), "r"(a1), "r"(a2), "r"(a3), "r"(b0), "r"(b1))

// ---------------------------------------------------------------------------
// Elementwise 3-way bf16 split
// ---------------------------------------------------------------------------
__global__ void split3_kernel(const float* __restrict__ in,
                              __nv_bfloat16* __restrict__ o1,
                              __nv_bfloat16* __restrict__ o2,
                              __nv_bfloat16* __restrict__ o3, int n4)
{
    int i = blockIdx.x * blockDim.x + threadIdx.x;
    if (i >= n4) return;
    float4 v = ((const float4*)in)[i];
    float val[4] = {v.x, v.y, v.z, v.w};
    __nv_bfloat16 h1[4], h2[4], h3[4];
#pragma unroll
    for (int j = 0; j < 4; j++) {
        h1[j] = __float2bfloat16_rn(val[j]);
        float r = val[j] - __bfloat162float(h1[j]);
        h2[j] = __float2bfloat16_rn(r);
        r -= __bfloat162float(h2[j]);
        h3[j] = __float2bfloat16_rn(r);
    }
    ((__nv_bfloat162*)o1)[2 * i]     = __nv_bfloat162(h1[0], h1[1]);
    ((__nv_bfloat162*)o1)[2 * i + 1] = __nv_bfloat162(h1[2], h1[3]);
    ((__nv_bfloat162*)o2)[2 * i]     = __nv_bfloat162(h2[0], h2[1]);
    ((__nv_bfloat162*)o2)[2 * i + 1] = __nv_bfloat162(h2[2], h2[3]);
    ((__nv_bfloat162*)o3)[2 * i]     = __nv_bfloat162(h3[0], h3[1]);
    ((__nv_bfloat162*)o3)[2 * i + 1] = __nv_bfloat162(h3[2], h3[3]);
}

// ---------------------------------------------------------------------------
// V transpose + 2-way split: V[b][m][e] (fp32) -> vth[b][e][m] (bf16 hi/lo)
// ---------------------------------------------------------------------------
__global__ void transpose_split2_kernel()
{
    __shared__ float tile[32][33];
    int b = blockIdx.z;
    int m0 = blockIdx.x * 32, e0 = blockIdx.y * 32;
    int tx = threadIdx.x, ty = threadIdx.y;
#pragma unroll
    for (int j = 0; j < 4; j++) {
        int m = m0 + ty + j * 8;
        tile[ty + j * 8][tx] = g_v[((size_t)(b * NSEQ + m)) * DIM + e0 + tx];
    }
    __syncthreads();
#pragma unroll
    for (int j = 0; j < 4; j++) {
        int e = e0 + ty + j * 8;
        float val = tile[tx][ty + j * 8];
        __nv_bfloat16 h1 = __float2bfloat16_rn(val);
        __nv_bfloat16 h2 = __float2bfloat16_rn(val - __bfloat162float(h1));
        size_t idx = ((size_t)b * DIM + e) * NSEQ + m0 + tx;
        g_vth[0][idx] = h1;
        g_vth[1][idx] = h2;
    }
}

// ---------------------------------------------------------------------------
// Softmax over rows of S; writes 2-way bf16 split P
// ---------------------------------------------------------------------------
__global__ __launch_bounds__(256) void softmax_kernel()
{
    __shared__ float red[8];
    const float* S = g_s + (size_t)blockIdx.x * NSEQ;
    const int tid = threadIdx.x, lane = tid & 31, wid = tid >> 5;

    float4 v0 = *(const float4*)(S + tid * 8);
    float4 v1 = *(const float4*)(S + tid * 8 + 4);
    float e[8] = {v0.x, v0.y, v0.z, v0.w, v1.x, v1.y, v1.z, v1.w};

    float m = e[0];
#pragma unroll
    for (int i = 1; i < 8; i++) m = fmaxf(m, e[i]);
#pragma unroll
    for (int off = 16; off > 0; off >>= 1) m = fmaxf(m, __shfl_xor_sync(~0u, m, off));
    if (lane == 0) red[wid] = m;
    __syncthreads();
    float bm = red[0];
#pragma unroll
    for (int i = 1; i < 8; i++) bm = fmaxf(bm, red[i]);
    __syncthreads();

    float s = 0.f;
#pragma unroll
    for (int i = 0; i < 8; i++) { e[i] = __expf(e[i] - bm); s += e[i]; }
#pragma unroll
    for (int off = 16; off > 0; off >>= 1) s += __shfl_xor_sync(~0u, s, off);
    if (lane == 0) red[wid] = s;
    __syncthreads();
    float bs = 0.f;
#pragma unroll
    for (int i = 0; i < 8; i++) bs += red[i];
    float inv = 1.0f / bs;

    size_t base = (size_t)blockIdx.x * NSEQ + tid * 8;
    __nv_bfloat16 h1[8], h2[8];
#pragma unroll
    for (int i = 0; i < 8; i++) {
        float p = e[i] * inv;
        h1[i] = __float2bfloat16_rn(p);
        h2[i] = __float2bfloat16_rn(p - __bfloat162float(h1[i]));
    }
#pragma unroll
    for (int i = 0; i < 4; i++) {
        ((__nv_bfloat162*)(g_ph[0] + base))[i] = __nv_bfloat162(h1[2 * i], h1[2 * i + 1]);
        ((__nv_bfloat162*)(g_ph[1] + base))[i] = __nv_bfloat162(h2[2 * i], h2[2 * i + 1]);
    }
}

// ---------------------------------------------------------------------------
// Generic mma.sync NT GEMM: C[m,n] = sum_pairs sum_k A_p[m,k] * B_p[n,k] (+bias[n])
// MODE 0: fp32 output.  MODE 3: 3-way bf16 split output.
// 256 threads, warp grid 4(m) x 2(n): each warp computes 32x64.
// ---------------------------------------------------------------------------
struct GemmArgs {
    const __nv_bfloat16* A[6];
    const __nv_bfloat16* B[6];
    long long batchA, batchB, batchC;
    int npairs, K, lda, ldb, ldc;
    float* Cf;
    __nv_bfloat16 *C1, *C2, *C3;
    const float* bias;
};

template <int MODE>
__global__ __launch_bounds__(NTHREADS)
void gemm_kernel(GemmArgs ga)
{
    __shared__ __align__(16) char sm_A[2][TILE_SM];
    __shared__ __align__(16) char sm_B[2][TILE_SM];

    const int tid  = threadIdx.x;
    const int wid  = tid >> 5;
    const int lane = tid & 31;
    const int nt = blockIdx.x, mt = blockIdx.y, bz = blockIdx.z;

    const int warp_m = wid & 3;       // 0..3 -> 32 rows each
    const int warp_n = wid >> 2;      // 0..1 -> 64 cols each
    const int m_base = warp_m * 32;
    const int n_base = warp_n * 64;

    const uint32_t sA0 = smem_u32(sm_A);
    const uint32_t sB0 = smem_u32(sm_B);

    const int KCH = ga.K / BK;
    const int NIT = ga.npairs * KCH;

    float acc[2][8][4];
#pragma unroll
    for (int i = 0; i < 2; i++)
#pragma unroll
        for (int j = 0; j < 8; j++)
#pragma unroll
            for (int r = 0; r < 4; r++) acc[i][j][r] = 0.f;

    // loader: 512 16B-chunks per operand, 2 per thread
    const int lrow0 = tid >> 2;          // +64 for second chunk
    const int lc16  = tid & 3;

    auto load_stage = [&](int it, int s) {
        int p = it / KCH, k0 = (it % KCH) * BK;
        const __nv_bfloat16* Ab = ga.A[p] + (size_t)bz * ga.batchA + k0;
        const __nv_bfloat16* Bb = ga.B[p] + (size_t)bz * ga.batchB + k0;
        uint32_t dA = sA0 + s * TILE_SM;
        uint32_t dB = sB0 + s * TILE_SM;
#pragma unroll
        for (int h = 0; h < 2; h++) {
            int r = lrow0 + h * 64;
            cp16(dA + r * ROWB + lc16 * 16,
                 Ab + (size_t)(mt * BM + r) * ga.lda + lc16 * 8);
            cp16(dB + r * ROWB + lc16 * 16,
                 Bb + (size_t)(nt * BN + r) * ga.ldb + lc16 * 8);
        }
        cp_commit();
    };

    load_stage(0, 0);

    for (int it = 0; it < NIT; it++) {
        int s = it & 1;
        if (it + 1 < NIT) { load_stage(it + 1, s ^ 1); cp_wait1(); }
        else              { cp_wait0(); }
        __syncthreads();

        uint32_t bA = sA0 + s * TILE_SM;
        uint32_t bB = sB0 + s * TILE_SM;
#pragma unroll
        for (int ks = 0; ks < 2; ks++) {
            // A fragments: 2 m16-tiles
            uint32_t a[2][4];
#pragma unroll
            for (int mi = 0; mi < 2; mi++) {
                int row = m_base + mi * 16 + (lane & 15);
                int kc  = ks * 16 + (lane >> 4) * 8;
                LDSM4(a[mi][0], a[mi][1], a[mi][2], a[mi][3],
                      bA + row * ROWB + kc * 2);
            }
            // B fragments: 8 n8-tiles via 4 ldmatrix.x4
            uint32_t b[8][2];
#pragma unroll
            for (int j2 = 0; j2 < 4; j2++) {
                int grp = lane >> 3;
                int row = n_base + j2 * 16 + ((grp >> 1) * 8) + (lane & 7);
                int kc  = ks * 16 + (grp & 1) * 8;
                uint32_t r0, r1, r2, r3;
                LDSM4(r0, r1, r2, r3, bB + row * ROWB + kc * 2);
                b[2 * j2][0] = r0; b[2 * j2][1] = r1;
                b[2 * j2 + 1][0] = r2; b[2 * j2 + 1][1] = r3;
            }
#pragma unroll
            for (int mi = 0; mi < 2; mi++)
#pragma unroll
                for (int nj = 0; nj < 8; nj++)
                    MMA16816(acc[mi][nj][0], acc[mi][nj][1], acc[mi][nj][2], acc[mi][nj][3],
                             a[mi][0], a[mi][1], a[mi][2], a[mi][3],
                             b[nj][0], b[nj][1]);
        }
        __syncthreads();
    }

    // Epilogue. Thread t of warp holds, per (mi,nj):
    //   c0,c1 -> (row, col), (row, col+1); c2,c3 -> (row+8, col..)
    //   row = m_base + mi*16 + lane/4 ; col = n_base + nj*8 + 2*(lane%4)
    const int r0l = lane >> 2;
    const int c0l = (lane & 3) * 2;
#pragma unroll
    for (int mi = 0; mi < 2; mi++) {
#pragma unroll
        for (int half = 0; half < 2; half++) {
            int grow = mt * BM + m_base + mi * 16 + r0l + half * 8;
#pragma unroll
            for (int nj = 0; nj < 8; nj++) {
                int gcol = nt * BN + n_base + nj * 8 + c0l;
                float v0 = acc[mi][nj][2 * half];
                float v1 = acc[mi][nj][2 * half + 1];
                if (ga.bias) { v0 += ga.bias[gcol]; v1 += ga.bias[gcol + 1]; }
                if (MODE == 0) {
                    float* C = ga.Cf + (size_t)bz * ga.batchC + (size_t)grow * ga.ldc + gcol;
                    *(float2*)C = make_float2(v0, v1);
                } else {
                    size_t off = (size_t)grow * ga.ldc + gcol;
                    __nv_bfloat16 a1 = __float2bfloat16_rn(v0);
                    float ra = v0 - __bfloat162float(a1);
                    __nv_bfloat16 a2 = __float2bfloat16_rn(ra);
                    __nv_bfloat16 a3 = __float2bfloat16_rn(ra - __bfloat162float(a2));
                    __nv_bfloat16 b1 = __float2bfloat16_rn(v1);
                    float rb = v1 - __bfloat162float(b1);
                    __nv_bfloat16 b2 = __float2bfloat16_rn(rb);
                    __nv_bfloat16 b3 = __float2bfloat16_rn(rb - __bfloat162float(b2));
                    *(__nv_bfloat162*)(ga.C1 + off) = __nv_bfloat162(a1, b1);
                    *(__nv_bfloat162*)(ga.C2 + off) = __nv_bfloat162(a2, b2);
                    *(__nv_bfloat162*)(ga.C3 + off) = __nv_bfloat162(a3, b3);
                }
            }
        }
    }
}

// ---------------------------------------------------------------------------
extern "C" void kernel_launch(void* const* d_in, const int* in_sizes, int n_in,
                              void* d_out, int out_size)
{
    const float* x  = (const float*)d_in[0];
    const float* Wq = (const float*)d_in[1];
    const float* bq = (const float*)d_in[2];
    const float* Wk = (const float*)d_in[3];
    const float* bk = (const float*)d_in[4];
    const float* Wv = (const float*)d_in[5];
    const float* bv = (const float*)d_in[6];
    float* out = (float*)d_out;

    void* p;
    cudaGetSymbolAddress(&p, g_xh);  __nv_bfloat16* xh = (__nv_bfloat16*)p;
    cudaGetSymbolAddress(&p, g_wqh); __nv_bfloat16* wqh = (__nv_bfloat16*)p;
    cudaGetSymbolAddress(&p, g_wkh); __nv_bfloat16* wkh = (__nv_bfloat16*)p;
    cudaGetSymbolAddress(&p, g_wvh); __nv_bfloat16* wvh = (__nv_bfloat16*)p;
    cudaGetSymbolAddress(&p, g_qh);  __nv_bfloat16* qh = (__nv_bfloat16*)p;
    cudaGetSymbolAddress(&p, g_kh);  __nv_bfloat16* kh = (__nv_bfloat16*)p;
    cudaGetSymbolAddress(&p, g_v);   float* vptr = (float*)p;
    cudaGetSymbolAddress(&p, g_vth); __nv_bfloat16* vth = (__nv_bfloat16*)p;
    cudaGetSymbolAddress(&p, g_s);   float* sptr = (float*)p;
    cudaGetSymbolAddress(&p, g_ph);  __nv_bfloat16* ph = (__nv_bfloat16*)p;

    // 1) splits of x and weights
    split3_kernel<<<(XSZ / 4 + 255) / 256, 256>>>(x,  xh,  xh + XSZ,  xh + 2 * XSZ, XSZ / 4);
    split3_kernel<<<(WSZ / 4 + 255) / 256, 256>>>(Wq, wqh, wqh + WSZ, wqh + 2 * WSZ, WSZ / 4);
    split3_kernel<<<(WSZ / 4 + 255) / 256, 256>>>(Wk, wkh, wkh + WSZ, wkh + 2 * WSZ, WSZ / 4);
    split3_kernel<<<(WSZ / 4 + 255) / 256, 256>>>(Wv, wvh, wvh + WSZ, wvh + 2 * WSZ, WSZ / 4);

    const int P6a[6] = {0, 0, 1, 1, 0, 2}, P6b[6] = {0, 1, 0, 1, 2, 0};
    const int P3a[3] = {0, 0, 1},          P3b[3] = {0, 1, 0};

    // 2) Q and K projections (6 pairs, 3-split epilogue)
    {
        GemmArgs ga = {};
        for (int i = 0; i < 6; i++) { ga.A[i] = xh + (size_t)P6a[i] * XSZ; ga.B[i] = wqh + (size_t)P6b[i] * WSZ; }
        ga.batchA = ga.batchB = ga.batchC = 0;
        ga.npairs = 6; ga.K = DIM; ga.lda = DIM; ga.ldb = DIM; ga.ldc = DIM;
        ga.C1 = qh; ga.C2 = qh + XSZ; ga.C3 = qh + 2 * XSZ; ga.bias = bq;
        gemm_kernel<3><<<dim3(DIM / BN, ROWS / BM, 1), NTHREADS>>>(ga);
        for (int i = 0; i < 6; i++) ga.B[i] = wkh + (size_t)P6b[i] * WSZ;
        ga.C1 = kh; ga.C2 = kh + XSZ; ga.C3 = kh + 2 * XSZ; ga.bias = bk;
        gemm_kernel<3><<<dim3(DIM / BN, ROWS / BM, 1), NTHREADS>>>(ga);
    }
    // 3) V projection (3 pairs, fp32)
    {
        GemmArgs ga = {};
        for (int i = 0; i < 3; i++) { ga.A[i] = xh + (size_t)P3a[i] * XSZ; ga.B[i] = wvh + (size_t)P3b[i] * WSZ; }
        ga.batchA = ga.batchB = ga.batchC = 0;
        ga.npairs = 3; ga.K = DIM; ga.lda = DIM; ga.ldb = DIM; ga.ldc = DIM;
        ga.Cf = vptr; ga.bias = bv;
        gemm_kernel<0><<<dim3(DIM / BN, ROWS / BM, 1), NTHREADS>>>(ga);
    }
    // 4) V transpose + 2-split
    transpose_split2_kernel<<<dim3(NSEQ / 32, DIM / 32, BATCH), dim3(32, 8)>>>();

    // 5) scores S = Q K^T (6 pairs, fp32)
    {
        GemmArgs ga = {};
        for (int i = 0; i < 6; i++) { ga.A[i] = qh + (size_t)P6a[i] * XSZ; ga.B[i] = kh + (size_t)P6b[i] * XSZ; }
        ga.batchA = ga.batchB = (long long)NSEQ * DIM;
        ga.batchC = (long long)NSEQ * NSEQ;
        ga.npairs = 6; ga.K = DIM; ga.lda = DIM; ga.ldb = DIM; ga.ldc = NSEQ;
        ga.Cf = sptr; ga.bias = nullptr;
        gemm_kernel<0><<<dim3(NSEQ / BN, NSEQ / BM, BATCH), NTHREADS>>>(ga);
    }
    // 6) softmax -> 2-split P
    softmax_kernel<<<BATCH * NSEQ, 256>>>();

    // 7) O = P V (3 pairs, fp32)
    {
        GemmArgs ga = {};
        for (int i = 0; i < 3; i++) {
            ga.A[i] = ph + (size_t)P3a[i] * (size_t)(SSZ);
            ga.B[i] = vth + (size_t)P3b[i] * ((size_t)BATCH * DIM * NSEQ);
        }
        ga.batchA = (long long)NSEQ * NSEQ;
        ga.batchB = (long long)DIM * NSEQ;
        ga.batchC = (long long)NSEQ * DIM;
        ga.npairs = 3; ga.K = NSEQ; ga.lda = NSEQ; ga.ldb = NSEQ; ga.ldc = DIM;
        ga.Cf = out; ga.bias = nullptr;
        gemm_kernel<0><<<dim3(DIM / BN, NSEQ / BM, BATCH), NTHREADS>>>(ga);
    }
}

// round 6
// speedup vs baseline: 1.2922x; 1.0329x over previous
#include <cuda_runtime.h>
#include <cuda_fp16.h>
#include <cstdint>

#define BATCH 8
#define NSEQ  2048
#define DIM   512
#define ROWS  (BATCH * NSEQ)   // 16384

// ---- mma.sync GEMM tiling ----
#define BM 128
#define BN 128
#define BK 32
#define NTHREADS 128
#define ROWB 80                 // smem row stride in bytes (conflict-free, 16B aligned)
#define TILE_SM (128 * ROWB)    // 10240 B per operand buffer

#define XSZ (ROWS * DIM)
#define WSZ (DIM * DIM)
#define SSZ ((size_t)BATCH * NSEQ * NSEQ)

// ---------------------------------------------------------------------------
// Scratch (allocation-free rule: __device__ globals)
// ---------------------------------------------------------------------------
__device__ __half g_xh[2][XSZ];
__device__ __half g_wqh[2][WSZ];
__device__ __half g_wkh[2][WSZ];
__device__ __half g_wvh[2][WSZ];
__device__ __half g_qh[2][XSZ];
__device__ __half g_kh[2][XSZ];
__device__ float  g_v[XSZ];
__device__ __half g_vth[2][(size_t)BATCH * DIM * NSEQ];
__device__ float  g_s[SSZ];
__device__ __half g_ph[2][SSZ];

// ---------------------------------------------------------------------------
// PTX helpers
// ---------------------------------------------------------------------------
static __device__ __forceinline__ uint32_t smem_u32(const void* p) {
    uint32_t a;
    asm("{ .reg .u64 t; cvta.to.shared.u64 t, %1; cvt.u32.u64 %0, t; }" : "=r"(a) : "l"(p));
    return a;
}
static __device__ __forceinline__ void cp16(uint32_t saddr, const void* g) {
    asm volatile("cp.async.cg.shared.global [%0], [%1], 16;" :: "r"(saddr), "l"(g));
}
static __device__ __forceinline__ void cp_commit() {
    asm volatile("cp.async.commit_group;" ::: "memory");
}
static __device__ __forceinline__ void cp_wait0() {
    asm volatile("cp.async.wait_group 0;" ::: "memory");
}
static __device__ __forceinline__ void cp_wait1() {
    asm volatile("cp.async.wait_group 1;" ::: "memory");
}
#define LDSM4(R0, R1, R2, R3, addr) \
    asm volatile("ldmatrix.sync.aligned.m8n8.x4.shared.b16 {%0,%1,%2,%3}, [%4];" \
                 : "=r"(R0), "=r"(R1), "=r"(R2), "=r"(R3) : "r"(addr))
#define MMA16816(c0, c1, c2, c3, a0, a1, a2, a3, b0, b1) \
    asm volatile("mma.sync.aligned.m16n8k16.row.col.f32.f16.f16.f32 " \
                 "{%0,%1,%2,%3}, {%4,%5,%6,%7}, {%8,%9}, {%0,%1,%2,%3};" \
                 : "+f"(c0), "+f"(c1), "+f"(c2), "+f"(c3) \
                 : "r"(a0), "r"(a1), "r"(a2), "r"(a3), "r"(b0), "r"(b1))

// ---------------------------------------------------------------------------
// Elementwise 2-way fp16 split
// ---------------------------------------------------------------------------
__global__ void split2_kernel(const float* __restrict__ in,
                              __half* __restrict__ o1,
                              __half* __restrict__ o2, int n4)
{
    int i = blockIdx.x * blockDim.x + threadIdx.x;
    if (i >= n4) return;
    float4 v = ((const float4*)in)[i];
    float val[4] = {v.x, v.y, v.z, v.w};
    __half h1[4], h2[4];
#pragma unroll
    for (int j = 0; j < 4; j++) {
        h1[j] = __float2half_rn(val[j]);
        h2[j] = __float2half_rn(val[j] - __half2float(h1[j]));
    }
    ((__half2*)o1)[2 * i]     = __halves2half2(h1[0], h1[1]);
    ((__half2*)o1)[2 * i + 1] = __halves2half2(h1[2], h1[3]);
    ((__half2*)o2)[2 * i]     = __halves2half2(h2[0], h2[1]);
    ((__half2*)o2)[2 * i + 1] = __halves2half2(h2[2], h2[3]);
}

// ---------------------------------------------------------------------------
// V transpose + 2-way fp16 split: V[b][m][e] (fp32) -> vth[b][e][m]
// ---------------------------------------------------------------------------
__global__ void transpose_split2_kernel()
{
    __shared__ float tile[32][33];
    int b = blockIdx.z;
    int m0 = blockIdx.x * 32, e0 = blockIdx.y * 32;
    int tx = threadIdx.x, ty = threadIdx.y;
#pragma unroll
    for (int j = 0; j < 4; j++) {
        int m = m0 + ty + j * 8;
        tile[ty + j * 8][tx] = g_v[((size_t)(b * NSEQ + m)) * DIM + e0 + tx];
    }
    __syncthreads();
#pragma unroll
    for (int j = 0; j < 4; j++) {
        int e = e0 + ty + j * 8;
        float val = tile[tx][ty + j * 8];
        __half h1 = __float2half_rn(val);
        __half h2 = __float2half_rn(val - __half2float(h1));
        size_t idx = ((size_t)b * DIM + e) * NSEQ + m0 + tx;
        g_vth[0][idx] = h1;
        g_vth[1][idx] = h2;
    }
}

// ---------------------------------------------------------------------------
// Softmax over rows of S; writes 2-way fp16 split P
// ---------------------------------------------------------------------------
__global__ __launch_bounds__(256) void softmax_kernel()
{
    __shared__ float red[8];
    const float* S = g_s + (size_t)blockIdx.x * NSEQ;
    const int tid = threadIdx.x, lane = tid & 31, wid = tid >> 5;

    float4 v0 = *(const float4*)(S + tid * 8);
    float4 v1 = *(const float4*)(S + tid * 8 + 4);
    float e[8] = {v0.x, v0.y, v0.z, v0.w, v1.x, v1.y, v1.z, v1.w};

    float m = e[0];
#pragma unroll
    for (int i = 1; i < 8; i++) m = fmaxf(m, e[i]);
#pragma unroll
    for (int off = 16; off > 0; off >>= 1) m = fmaxf(m, __shfl_xor_sync(~0u, m, off));
    if (lane == 0) red[wid] = m;
    __syncthreads();
    float bm = red[0];
#pragma unroll
    for (int i = 1; i < 8; i++) bm = fmaxf(bm, red[i]);
    __syncthreads();

    float s = 0.f;
#pragma unroll
    for (int i = 0; i < 8; i++) { e[i] = __expf(e[i] - bm); s += e[i]; }
#pragma unroll
    for (int off = 16; off > 0; off >>= 1) s += __shfl_xor_sync(~0u, s, off);
    if (lane == 0) red[wid] = s;
    __syncthreads();
    float bs = 0.f;
#pragma unroll
    for (int i = 0; i < 8; i++) bs += red[i];
    float inv = 1.0f / bs;

    size_t base = (size_t)blockIdx.x * NSEQ + tid * 8;
    __half h1[8], h2[8];
#pragma unroll
    for (int i = 0; i < 8; i++) {
        float p = e[i] * inv;
        h1[i] = __float2half_rn(p);
        h2[i] = __float2half_rn(p - __half2float(h1[i]));
    }
#pragma unroll
    for (int i = 0; i < 4; i++) {
        ((__half2*)(g_ph[0] + base))[i] = __halves2half2(h1[2 * i], h1[2 * i + 1]);
        ((__half2*)(g_ph[1] + base))[i] = __halves2half2(h2[2 * i], h2[2 * i + 1]);
    }
}

// ---------------------------------------------------------------------------
// Generic mma.sync NT GEMM: C[m,n] = sum_pairs sum_k A_p[m,k] * B_p[n,k] (+bias[n])
// MODE 0: fp32 output.  MODE 2: 2-way fp16 split output.
// 128 threads, warp grid 2(m) x 2(n): each warp computes 64x64.
// ---------------------------------------------------------------------------
struct GemmArgs {
    const __half* A[3];
    const __half* B[3];
    long long batchA, batchB, batchC;
    int npairs, K, lda, ldb, ldc;
    float* Cf;
    __half *C1, *C2;
    const float* bias;
};

template <int MODE>
__global__ __launch_bounds__(NTHREADS)
void gemm_kernel(GemmArgs ga)
{
    __shared__ __align__(16) char sm_A[2][TILE_SM];
    __shared__ __align__(16) char sm_B[2][TILE_SM];

    const int tid  = threadIdx.x;
    const int wid  = tid >> 5;
    const int lane = tid & 31;
    const int nt = blockIdx.x, mt = blockIdx.y, bz = blockIdx.z;

    const int warp_m = wid & 1;       // 0..1 -> 64 rows each
    const int warp_n = wid >> 1;      // 0..1 -> 64 cols each
    const int m_base = warp_m * 64;
    const int n_base = warp_n * 64;

    const uint32_t sA0 = smem_u32(sm_A);
    const uint32_t sB0 = smem_u32(sm_B);

    const int KCH = ga.K / BK;
    const int NIT = ga.npairs * KCH;

    float acc[4][8][4];
#pragma unroll
    for (int i = 0; i < 4; i++)
#pragma unroll
        for (int j = 0; j < 8; j++)
#pragma unroll
            for (int r = 0; r < 4; r++) acc[i][j][r] = 0.f;

    // loader: 512 16B-chunks per operand, 4 per thread
    const int lrow0 = tid >> 2;          // +32 per extra chunk
    const int lc16  = tid & 3;

    auto load_stage = [&](int it, int s) {
        int p = it / KCH, k0 = (it % KCH) * BK;
        const __half* Ab = ga.A[p] + (size_t)bz * ga.batchA + k0;
        const __half* Bb = ga.B[p] + (size_t)bz * ga.batchB + k0;
        uint32_t dA = sA0 + s * TILE_SM;
        uint32_t dB = sB0 + s * TILE_SM;
#pragma unroll
        for (int h = 0; h < 4; h++) {
            int r = lrow0 + h * 32;
            cp16(dA + r * ROWB + lc16 * 16,
                 Ab + (size_t)(mt * BM + r) * ga.lda + lc16 * 8);
            cp16(dB + r * ROWB + lc16 * 16,
                 Bb + (size_t)(nt * BN + r) * ga.ldb + lc16 * 8);
        }
        cp_commit();
    };

    load_stage(0, 0);

    for (int it = 0; it < NIT; it++) {
        int s = it & 1;
        if (it + 1 < NIT) { load_stage(it + 1, s ^ 1); cp_wait1(); }
        else              { cp_wait0(); }
        __syncthreads();

        uint32_t bA = sA0 + s * TILE_SM;
        uint32_t bB = sB0 + s * TILE_SM;
#pragma unroll
        for (int ks = 0; ks < 2; ks++) {
            // A fragments: 4 m16-tiles
            uint32_t a[4][4];
#pragma unroll
            for (int mi = 0; mi < 4; mi++) {
                int row = m_base + mi * 16 + (lane & 15);
                int kc  = ks * 16 + (lane >> 4) * 8;
                LDSM4(a[mi][0], a[mi][1], a[mi][2], a[mi][3],
                      bA + row * ROWB + kc * 2);
            }
            // B fragments: 8 n8-tiles via 4 ldmatrix.x4
            uint32_t b[8][2];
#pragma unroll
            for (int j2 = 0; j2 < 4; j2++) {
                int grp = lane >> 3;
                int row = n_base + j2 * 16 + ((grp >> 1) * 8) + (lane & 7);
                int kc  = ks * 16 + (grp & 1) * 8;
                uint32_t r0, r1, r2, r3;
                LDSM4(r0, r1, r2, r3, bB + row * ROWB + kc * 2);
                b[2 * j2][0] = r0; b[2 * j2][1] = r1;
                b[2 * j2 + 1][0] = r2; b[2 * j2 + 1][1] = r3;
            }
#pragma unroll
            for (int mi = 0; mi < 4; mi++)
#pragma unroll
                for (int nj = 0; nj < 8; nj++)
                    MMA16816(acc[mi][nj][0], acc[mi][nj][1], acc[mi][nj][2], acc[mi][nj][3],
                             a[mi][0], a[mi][1], a[mi][2], a[mi][3],
                             b[nj][0], b[nj][1]);
        }
        __syncthreads();
    }

    // Epilogue. Thread t of warp holds, per (mi,nj):
    //   c0,c1 -> (row, col), (row, col+1); c2,c3 -> (row+8, col..)
    const int r0l = lane >> 2;
    const int c0l = (lane & 3) * 2;
#pragma unroll
    for (int mi = 0; mi < 4; mi++) {
#pragma unroll
        for (int half = 0; half < 2; half++) {
            int grow = mt * BM + m_base + mi * 16 + r0l + half * 8;
#pragma unroll
            for (int nj = 0; nj < 8; nj++) {
                int gcol = nt * BN + n_base + nj * 8 + c0l;
                float v0 = acc[mi][nj][2 * half];
                float v1 = acc[mi][nj][2 * half + 1];
                if (ga.bias) { v0 += ga.bias[gcol]; v1 += ga.bias[gcol + 1]; }
                if (MODE == 0) {
                    float* C = ga.Cf + (size_t)bz * ga.batchC + (size_t)grow * ga.ldc + gcol;
                    *(float2*)C = make_float2(v0, v1);
                } else {
                    size_t off = (size_t)grow * ga.ldc + gcol;
                    __half a1 = __float2half_rn(v0);
                    __half a2 = __float2half_rn(v0 - __half2float(a1));
                    __half b1 = __float2half_rn(v1);
                    __half b2 = __float2half_rn(v1 - __half2float(b1));
                    *(__half2*)(ga.C1 + off) = __halves2half2(a1, b1);
                    *(__half2*)(ga.C2 + off) = __halves2half2(a2, b2);
                }
            }
        }
    }
}

// ---------------------------------------------------------------------------
extern "C" void kernel_launch(void* const* d_in, const int* in_sizes, int n_in,
                              void* d_out, int out_size)
{
    const float* x  = (const float*)d_in[0];
    const float* Wq = (const float*)d_in[1];
    const float* bq = (const float*)d_in[2];
    const float* Wk = (const float*)d_in[3];
    const float* bk = (const float*)d_in[4];
    const float* Wv = (const float*)d_in[5];
    const float* bv = (const float*)d_in[6];
    float* out = (float*)d_out;

    void* p;
    cudaGetSymbolAddress(&p, g_xh);  __half* xh = (__half*)p;
    cudaGetSymbolAddress(&p, g_wqh); __half* wqh = (__half*)p;
    cudaGetSymbolAddress(&p, g_wkh); __half* wkh = (__half*)p;
    cudaGetSymbolAddress(&p, g_wvh); __half* wvh = (__half*)p;
    cudaGetSymbolAddress(&p, g_qh);  __half* qh = (__half*)p;
    cudaGetSymbolAddress(&p, g_kh);  __half* kh = (__half*)p;
    cudaGetSymbolAddress(&p, g_v);   float* vptr = (float*)p;
    cudaGetSymbolAddress(&p, g_vth); __half* vth = (__half*)p;
    cudaGetSymbolAddress(&p, g_s);   float* sptr = (float*)p;
    cudaGetSymbolAddress(&p, g_ph);  __half* ph = (__half*)p;

    // 1) 2-way fp16 splits of x and weights
    split2_kernel<<<(XSZ / 4 + 255) / 256, 256>>>(x,  xh,  xh + XSZ,  XSZ / 4);
    split2_kernel<<<(WSZ / 4 + 255) / 256, 256>>>(Wq, wqh, wqh + WSZ, WSZ / 4);
    split2_kernel<<<(WSZ / 4 + 255) / 256, 256>>>(Wk, wkh, wkh + WSZ, WSZ / 4);
    split2_kernel<<<(WSZ / 4 + 255) / 256, 256>>>(Wv, wvh, wvh + WSZ, WSZ / 4);

    const int Pa[3] = {0, 0, 1}, Pb[3] = {0, 1, 0};  // hi*hi, hi*lo, lo*hi

    // 2) Q and K projections (3 pairs, 2-split fp16 epilogue)
    {
        GemmArgs ga = {};
        for (int i = 0; i < 3; i++) { ga.A[i] = xh + (size_t)Pa[i] * XSZ; ga.B[i] = wqh + (size_t)Pb[i] * WSZ; }
        ga.batchA = ga.batchB = ga.batchC = 0;
        ga.npairs = 3; ga.K = DIM; ga.lda = DIM; ga.ldb = DIM; ga.ldc = DIM;
        ga.C1 = qh; ga.C2 = qh + XSZ; ga.bias = bq;
        gemm_kernel<2><<<dim3(DIM / BN, ROWS / BM, 1), NTHREADS>>>(ga);
        for (int i = 0; i < 3; i++) ga.B[i] = wkh + (size_t)Pb[i] * WSZ;
        ga.C1 = kh; ga.C2 = kh + XSZ; ga.bias = bk;
        gemm_kernel<2><<<dim3(DIM / BN, ROWS / BM, 1), NTHREADS>>>(ga);
    }
    // 3) V projection (3 pairs, fp32)
    {
        GemmArgs ga = {};
        for (int i = 0; i < 3; i++) { ga.A[i] = xh + (size_t)Pa[i] * XSZ; ga.B[i] = wvh + (size_t)Pb[i] * WSZ; }
        ga.batchA = ga.batchB = ga.batchC = 0;
        ga.npairs = 3; ga.K = DIM; ga.lda = DIM; ga.ldb = DIM; ga.ldc = DIM;
        ga.Cf = vptr; ga.bias = bv;
        gemm_kernel<0><<<dim3(DIM / BN, ROWS / BM, 1), NTHREADS>>>(ga);
    }
    // 4) V transpose + 2-split fp16
    transpose_split2_kernel<<<dim3(NSEQ / 32, DIM / 32, BATCH), dim3(32, 8)>>>();

    // 5) scores S = Q K^T (3 pairs, fp32)
    {
        GemmArgs ga = {};
        for (int i = 0; i < 3; i++) { ga.A[i] = qh + (size_t)Pa[i] * XSZ; ga.B[i] = kh + (size_t)Pb[i] * XSZ; }
        ga.batchA = ga.batchB = (long long)NSEQ * DIM;
        ga.batchC = (long long)NSEQ * NSEQ;
        ga.npairs = 3; ga.K = DIM; ga.lda = DIM; ga.ldb = DIM; ga.ldc = NSEQ;
        ga.Cf = sptr; ga.bias = nullptr;
        gemm_kernel<0><<<dim3(NSEQ / BN, NSEQ / BM, BATCH), NTHREADS>>>(ga);
    }
    // 6) softmax -> 2-split fp16 P
    softmax_kernel<<<BATCH * NSEQ, 256>>>();

    // 7) O = P V (3 pairs, fp32)
    {
        GemmArgs ga = {};
        for (int i = 0; i < 3; i++) {
            ga.A[i] = ph + (size_t)Pa[i] * (size_t)SSZ;
            ga.B[i] = vth + (size_t)Pb[i] * ((size_t)BATCH * DIM * NSEQ);
        }
        ga.batchA = (long long)NSEQ * NSEQ;
        ga.batchB = (long long)DIM * NSEQ;
        ga.batchC = (long long)NSEQ * DIM;
        ga.npairs = 3; ga.K = NSEQ; ga.lda = NSEQ; ga.ldb = NSEQ; ga.ldc = DIM;
        ga.Cf = out; ga.bias = nullptr;
        gemm_kernel<0><<<dim3(DIM / BN, NSEQ / BM, BATCH), NTHREADS>>>(ga);
    }
}

// round 11
// speedup vs baseline: 1.6776x; 1.2983x over previous
#include <cuda_runtime.h>
#include <cuda_fp16.h>
#include <cstdint>

#define BATCH 8
#define NSEQ  2048
#define DIM   512
#define ROWS  (BATCH * NSEQ)   // 16384

// ---- mma.sync GEMM tiling ----
#define BM 256
#define BN 128
#define BK 32
#define NTHREADS 256
#define ROWB 80                         // smem row stride (bytes): conflict-free, 16B aligned
#define A_SM (BM * ROWB)                // 20480
#define B_SM (BN * ROWB)                // 10240
#define STAGE_SM (A_SM + B_SM)          // 30720
#define NSTAGE 3
#define SMEM_TOTAL (NSTAGE * STAGE_SM)  // 92160

#define XSZ (ROWS * DIM)
#define WSZ (DIM * DIM)
#define SSZ ((size_t)BATCH * NSEQ * NSEQ)

// ---------------------------------------------------------------------------
// Scratch (allocation-free rule: __device__ globals)
// ---------------------------------------------------------------------------
__device__ __half g_xh[2][XSZ];
__device__ __half g_wqh[2][WSZ];
__device__ __half g_wkh[2][WSZ];
__device__ __half g_wvh[2][WSZ];
__device__ __half g_qh[2][XSZ];
__device__ __half g_kh[2][XSZ];
__device__ float  g_v[XSZ];
__device__ __half g_vth[2][(size_t)BATCH * DIM * NSEQ];
__device__ float  g_s[SSZ];
__device__ __half g_ph[2][SSZ];

// ---------------------------------------------------------------------------
// PTX helpers
// ---------------------------------------------------------------------------
static __device__ __forceinline__ uint32_t smem_u32(const void* p) {
    uint32_t a;
    asm("{ .reg .u64 t; cvta.to.shared.u64 t, %1; cvt.u32.u64 %0, t; }" : "=r"(a) : "l"(p));
    return a;
}
static __device__ __forceinline__ void cp16(uint32_t saddr, const void* g) {
    asm volatile("cp.async.cg.shared.global [%0], [%1], 16;" :: "r"(saddr), "l"(g));
}
static __device__ __forceinline__ void cp_commit() {
    asm volatile("cp.async.commit_group;" ::: "memory");
}
static __device__ __forceinline__ void cp_wait0() {
    asm volatile("cp.async.wait_group 0;" ::: "memory");
}
static __device__ __forceinline__ void cp_wait1() {
    asm volatile("cp.async.wait_group 1;" ::: "memory");
}
#define LDSM4(R0, R1, R2, R3, addr) \
    asm volatile("ldmatrix.sync.aligned.m8n8.x4.shared.b16 {%0,%1,%2,%3}, [%4];" \
                 : "=r"(R0), "=r"(R1), "=r"(R2), "=r"(R3) : "r"(addr))
#define MMA16816(c0, c1, c2, c3, a0, a1, a2, a3, b0, b1) \
    asm volatile("mma.sync.aligned.m16n8k16.row.col.f32.f16.f16.f32 " \
                 "{%0,%1,%2,%3}, {%4,%5,%6,%7}, {%8,%9}, {%0,%1,%2,%3};" \
                 : "+f"(c0), "+f"(c1), "+f"(c2), "+f"(c3) \
                 : "r"(a0), "r"(a1), "r"(a2), "r"(a3), "r"(b0), "r"(b1))

// ---------------------------------------------------------------------------
// Elementwise 2-way fp16 split
// ---------------------------------------------------------------------------
__global__ void split2_kernel(const float* __restrict__ in,
                              __half* __restrict__ o1,
                              __half* __restrict__ o2, int n4)
{
    int i = blockIdx.x * blockDim.x + threadIdx.x;
    if (i >= n4) return;
    float4 v = ((const float4*)in)[i];
    float val[4] = {v.x, v.y, v.z, v.w};
    __half h1[4], h2[4];
#pragma unroll
    for (int j = 0; j < 4; j++) {
        h1[j] = __float2half_rn(val[j]);
        h2[j] = __float2half_rn(val[j] - __half2float(h1[j]));
    }
    ((__half2*)o1)[2 * i]     = __halves2half2(h1[0], h1[1]);
    ((__half2*)o1)[2 * i + 1] = __halves2half2(h1[2], h1[3]);
    ((__half2*)o2)[2 * i]     = __halves2half2(h2[0], h2[1]);
    ((__half2*)o2)[2 * i + 1] = __halves2half2(h2[2], h2[3]);
}

// ---------------------------------------------------------------------------
// V transpose + 2-way fp16 split: V[b][m][e] (fp32) -> vth[b][e][m]
// ---------------------------------------------------------------------------
__global__ void transpose_split2_kernel()
{
    __shared__ float tile[32][33];
    int b = blockIdx.z;
    int m0 = blockIdx.x * 32, e0 = blockIdx.y * 32;
    int tx = threadIdx.x, ty = threadIdx.y;
#pragma unroll
    for (int j = 0; j < 4; j++) {
        int m = m0 + ty + j * 8;
        tile[ty + j * 8][tx] = g_v[((size_t)(b * NSEQ + m)) * DIM + e0 + tx];
    }
    __syncthreads();
#pragma unroll
    for (int j = 0; j < 4; j++) {
        int e = e0 + ty + j * 8;
        float val = tile[tx][ty + j * 8];
        __half h1 = __float2half_rn(val);
        __half h2 = __float2half_rn(val - __half2float(h1));
        size_t idx = ((size_t)b * DIM + e) * NSEQ + m0 + tx;
        g_vth[0][idx] = h1;
        g_vth[1][idx] = h2;
    }
}

// ---------------------------------------------------------------------------
// Softmax over rows of S; writes 2-way fp16 split P
// ---------------------------------------------------------------------------
__global__ __launch_bounds__(256) void softmax_kernel()
{
    __shared__ float red[8];
    const float* S = g_s + (size_t)blockIdx.x * NSEQ;
    const int tid = threadIdx.x, lane = tid & 31, wid = tid >> 5;

    float4 v0 = *(const float4*)(S + tid * 8);
    float4 v1 = *(const float4*)(S + tid * 8 + 4);
    float e[8] = {v0.x, v0.y, v0.z, v0.w, v1.x, v1.y, v1.z, v1.w};

    float m = e[0];
#pragma unroll
    for (int i = 1; i < 8; i++) m = fmaxf(m, e[i]);
#pragma unroll
    for (int off = 16; off > 0; off >>= 1) m = fmaxf(m, __shfl_xor_sync(~0u, m, off));
    if (lane == 0) red[wid] = m;
    __syncthreads();
    float bm = red[0];
#pragma unroll
    for (int i = 1; i < 8; i++) bm = fmaxf(bm, red[i]);
    __syncthreads();

    float s = 0.f;
#pragma unroll
    for (int i = 0; i < 8; i++) { e[i] = __expf(e[i] - bm); s += e[i]; }
#pragma unroll
    for (int off = 16; off > 0; off >>= 1) s += __shfl_xor_sync(~0u, s, off);
    if (lane == 0) red[wid] = s;
    __syncthreads();
    float bs = 0.f;
#pragma unroll
    for (int i = 0; i < 8; i++) bs += red[i];
    float inv = 1.0f / bs;

    size_t base = (size_t)blockIdx.x * NSEQ + tid * 8;
    __half h1[8], h2[8];
#pragma unroll
    for (int i = 0; i < 8; i++) {
        float p = e[i] * inv;
        h1[i] = __float2half_rn(p);
        h2[i] = __float2half_rn(p - __half2float(h1[i]));
    }
#pragma unroll
    for (int i = 0; i < 4; i++) {
        ((__half2*)(g_ph[0] + base))[i] = __halves2half2(h1[2 * i], h1[2 * i + 1]);
        ((__half2*)(g_ph[1] + base))[i] = __halves2half2(h2[2 * i], h2[2 * i + 1]);
    }
}

// ---------------------------------------------------------------------------
// Generic mma.sync NT GEMM: C[m,n] = sum_pairs sum_k A_p[m,k] * B_p[n,k] (+bias[n])
// MODE 0: fp32 output.  MODE 2: 2-way fp16 split output.
// 256 threads; warp grid 4(m) x 2(n); each warp computes 64x64.
// 3-stage cp.async pipeline, one __syncthreads per iteration.
// ---------------------------------------------------------------------------
struct GemmArgs {
    const __half* A[3];
    const __half* B[3];
    long long batchA, batchB, batchC;
    int npairs, K, lda, ldb, ldc;
    float* Cf;
    __half *C1, *C2;
    const float* bias;
};

template <int MODE>
__global__ __launch_bounds__(NTHREADS)
void gemm_kernel(GemmArgs ga)
{
    extern __shared__ __align__(16) char smem[];

    const int tid  = threadIdx.x;
    const int wid  = tid >> 5;
    const int lane = tid & 31;
    const int nt = blockIdx.x, mt = blockIdx.y, bz = blockIdx.z;

    const int m_base = (wid & 3) * 64;
    const int n_base = (wid >> 2) * 64;

    const uint32_t s0 = smem_u32(smem);

    const int KCH = ga.K / BK;
    const int NIT = ga.npairs * KCH;

    float acc[4][8][4];
#pragma unroll
    for (int i = 0; i < 4; i++)
#pragma unroll
        for (int j = 0; j < 8; j++)
#pragma unroll
            for (int r = 0; r < 4; r++) acc[i][j][r] = 0.f;

    const int lrow0 = tid >> 2;          // 0..63
    const int lc16  = tid & 3;           // 16B chunk within 64B row

    auto load_stage = [&](int it, int s) {
        int p = it / KCH, k0 = (it % KCH) * BK;
        const __half* Ab = ga.A[p] + (size_t)bz * ga.batchA + k0;
        const __half* Bb = ga.B[p] + (size_t)bz * ga.batchB + k0;
        uint32_t dA = s0 + s * STAGE_SM;
        uint32_t dB = dA + A_SM;
#pragma unroll
        for (int h = 0; h < 4; h++) {    // A: 256 rows
            int r = lrow0 + h * 64;
            cp16(dA + r * ROWB + lc16 * 16,
                 Ab + (size_t)(mt * BM + r) * ga.lda + lc16 * 8);
        }
#pragma unroll
        for (int h = 0; h < 2; h++) {    // B: 128 rows
            int r = lrow0 + h * 64;
            cp16(dB + r * ROWB + lc16 * 16,
                 Bb + (size_t)(nt * BN + r) * ga.ldb + lc16 * 8);
        }
        cp_commit();
    };

    load_stage(0, 0);
    load_stage(1, 1);

    for (int it = 0; it < NIT; it++) {
        if (it + 1 < NIT) cp_wait1(); else cp_wait0();
        __syncthreads();
        if (it + 2 < NIT) load_stage(it + 2, (it + 2) % NSTAGE);

        uint32_t bA = s0 + (it % NSTAGE) * STAGE_SM;
        uint32_t bB = bA + A_SM;
#pragma unroll
        for (int ks = 0; ks < 2; ks++) {
            uint32_t a[4][4];
#pragma unroll
            for (int mi = 0; mi < 4; mi++) {
                int row = m_base + mi * 16 + (lane & 15);
                int kc  = ks * 16 + (lane >> 4) * 8;
                LDSM4(a[mi][0], a[mi][1], a[mi][2], a[mi][3],
                      bA + row * ROWB + kc * 2);
            }
            uint32_t b[8][2];
#pragma unroll
            for (int j2 = 0; j2 < 4; j2++) {
                int grp = lane >> 3;
                int row = n_base + j2 * 16 + ((grp >> 1) * 8) + (lane & 7);
                int kc  = ks * 16 + (grp & 1) * 8;
                uint32_t r0, r1, r2, r3;
                LDSM4(r0, r1, r2, r3, bB + row * ROWB + kc * 2);
                b[2 * j2][0] = r0; b[2 * j2][1] = r1;
                b[2 * j2 + 1][0] = r2; b[2 * j2 + 1][1] = r3;
            }
#pragma unroll
            for (int mi = 0; mi < 4; mi++)
#pragma unroll
                for (int nj = 0; nj < 8; nj++)
                    MMA16816(acc[mi][nj][0], acc[mi][nj][1], acc[mi][nj][2], acc[mi][nj][3],
                             a[mi][0], a[mi][1], a[mi][2], a[mi][3],
                             b[nj][0], b[nj][1]);
        }
    }

    // Epilogue. Per (mi,nj): c0,c1 -> (row, col..col+1); c2,c3 -> (row+8, ..)
    const int r0l = lane >> 2;
    const int c0l = (lane & 3) * 2;
#pragma unroll
    for (int mi = 0; mi < 4; mi++) {
#pragma unroll
        for (int half = 0; half < 2; half++) {
            int grow = mt * BM + m_base + mi * 16 + r0l + half * 8;
#pragma unroll
            for (int nj = 0; nj < 8; nj++) {
                int gcol = nt * BN + n_base + nj * 8 + c0l;
                float v0 = acc[mi][nj][2 * half];
                float v1 = acc[mi][nj][2 * half + 1];
                if (ga.bias) { v0 += ga.bias[gcol]; v1 += ga.bias[gcol + 1]; }
                if (MODE == 0) {
                    float* C = ga.Cf + (size_t)bz * ga.batchC + (size_t)grow * ga.ldc + gcol;
                    *(float2*)C = make_float2(v0, v1);
                } else {
                    size_t off = (size_t)grow * ga.ldc + gcol;
                    __half a1 = __float2half_rn(v0);
                    __half a2 = __float2half_rn(v0 - __half2float(a1));
                    __half b1 = __float2half_rn(v1);
                    __half b2 = __float2half_rn(v1 - __half2float(b1));
                    *(__half2*)(ga.C1 + off) = __halves2half2(a1, b1);
                    *(__half2*)(ga.C2 + off) = __halves2half2(a2, b2);
                }
            }
        }
    }
}

// ---------------------------------------------------------------------------
extern "C" void kernel_launch(void* const* d_in, const int* in_sizes, int n_in,
                              void* d_out, int out_size)
{
    const float* x  = (const float*)d_in[0];
    const float* Wq = (const float*)d_in[1];
    const float* bq = (const float*)d_in[2];
    const float* Wk = (const float*)d_in[3];
    const float* bk = (const float*)d_in[4];
    const float* Wv = (const float*)d_in[5];
    const float* bv = (const float*)d_in[6];
    float* out = (float*)d_out;

    void* p;
    cudaGetSymbolAddress(&p, g_xh);  __half* xh = (__half*)p;
    cudaGetSymbolAddress(&p, g_wqh); __half* wqh = (__half*)p;
    cudaGetSymbolAddress(&p, g_wkh); __half* wkh = (__half*)p;
    cudaGetSymbolAddress(&p, g_wvh); __half* wvh = (__half*)p;
    cudaGetSymbolAddress(&p, g_qh);  __half* qh = (__half*)p;
    cudaGetSymbolAddress(&p, g_kh);  __half* kh = (__half*)p;
    cudaGetSymbolAddress(&p, g_v);   float* vptr = (float*)p;
    cudaGetSymbolAddress(&p, g_vth); __half* vth = (__half*)p;
    cudaGetSymbolAddress(&p, g_s);   float* sptr = (float*)p;
    cudaGetSymbolAddress(&p, g_ph);  __half* ph = (__half*)p;

    static bool attr_done = false;
    if (!attr_done) {
        cudaFuncSetAttribute((const void*)gemm_kernel<0>,
                             cudaFuncAttributeMaxDynamicSharedMemorySize, SMEM_TOTAL);
        cudaFuncSetAttribute((const void*)gemm_kernel<2>,
                             cudaFuncAttributeMaxDynamicSharedMemorySize, SMEM_TOTAL);
        attr_done = true;
    }

    // 1) 2-way fp16 splits of x and weights
    split2_kernel<<<(XSZ / 4 + 255) / 256, 256>>>(x,  xh,  xh + XSZ,  XSZ / 4);
    split2_kernel<<<(WSZ / 4 + 255) / 256, 256>>>(Wq, wqh, wqh + WSZ, WSZ / 4);
    split2_kernel<<<(WSZ / 4 + 255) / 256, 256>>>(Wk, wkh, wkh + WSZ, WSZ / 4);
    split2_kernel<<<(WSZ / 4 + 255) / 256, 256>>>(Wv, wvh, wvh + WSZ, WSZ / 4);

    const int Pa[3] = {0, 0, 1}, Pb[3] = {0, 1, 0};  // hi*hi, hi*lo, lo*hi

    // 2) Q and K projections (3 pairs, 2-split fp16 epilogue)
    {
        GemmArgs ga = {};
        for (int i = 0; i < 3; i++) { ga.A[i] = xh + (size_t)Pa[i] * XSZ; ga.B[i] = wqh + (size_t)Pb[i] * WSZ; }
        ga.batchA = ga.batchB = ga.batchC = 0;
        ga.npairs = 3; ga.K = DIM; ga.lda = DIM; ga.ldb = DIM; ga.ldc = DIM;
        ga.C1 = qh; ga.C2 = qh + XSZ; ga.bias = bq;
        gemm_kernel<2><<<dim3(DIM / BN, ROWS / BM, 1), NTHREADS, SMEM_TOTAL>>>(ga);
        for (int i = 0; i < 3; i++) ga.B[i] = wkh + (size_t)Pb[i] * WSZ;
        ga.C1 = kh; ga.C2 = kh + XSZ; ga.bias = bk;
        gemm_kernel<2><<<dim3(DIM / BN, ROWS / BM, 1), NTHREADS, SMEM_TOTAL>>>(ga);
    }
    // 3) V projection (3 pairs, fp32)
    {
        GemmArgs ga = {};
        for (int i = 0; i < 3; i++) { ga.A[i] = xh + (size_t)Pa[i] * XSZ; ga.B[i] = wvh + (size_t)Pb[i] * WSZ; }
        ga.batchA = ga.batchB = ga.batchC = 0;
        ga.npairs = 3; ga.K = DIM; ga.lda = DIM; ga.ldb = DIM; ga.ldc = DIM;
        ga.Cf = vptr; ga.bias = bv;
        gemm_kernel<0><<<dim3(DIM / BN, ROWS / BM, 1), NTHREADS, SMEM_TOTAL>>>(ga);
    }
    // 4) V transpose + 2-split fp16
    transpose_split2_kernel<<<dim3(NSEQ / 32, DIM / 32, BATCH), dim3(32, 8)>>>();

    // 5) scores S = Q K^T (3 pairs, fp32)
    {
        GemmArgs ga = {};
        for (int i = 0; i < 3; i++) { ga.A[i] = qh + (size_t)Pa[i] * XSZ; ga.B[i] = kh + (size_t)Pb[i] * XSZ; }
        ga.batchA = ga.batchB = (long long)NSEQ * DIM;
        ga.batchC = (long long)NSEQ * NSEQ;
        ga.npairs = 3; ga.K = DIM; ga.lda = DIM; ga.ldb = DIM; ga.ldc = NSEQ;
        ga.Cf = sptr; ga.bias = nullptr;
        gemm_kernel<0><<<dim3(NSEQ / BN, NSEQ / BM, BATCH), NTHREADS, SMEM_TOTAL>>>(ga);
    }
    // 6) softmax -> 2-split fp16 P
    softmax_kernel<<<BATCH * NSEQ, 256>>>();

    // 7) O = P V (3 pairs, fp32)
    {
        GemmArgs ga = {};
        for (int i = 0; i < 3; i++) {
            ga.A[i] = ph + (size_t)Pa[i] * (size_t)SSZ;
            ga.B[i] = vth + (size_t)Pb[i] * ((size_t)BATCH * DIM * NSEQ);
        }
        ga.batchA = (long long)NSEQ * NSEQ;
        ga.batchB = (long long)DIM * NSEQ;
        ga.batchC = (long long)NSEQ * DIM;
        ga.npairs = 3; ga.K = NSEQ; ga.lda = NSEQ; ga.ldb = NSEQ; ga.ldc = DIM;
        ga.Cf = out; ga.bias = nullptr;
        gemm_kernel<0><<<dim3(DIM / BN, NSEQ / BM, BATCH), NTHREADS, SMEM_TOTAL>>>(ga);
    }
}

// round 12
// speedup vs baseline: 2.2653x; 1.3503x over previous
#include <cuda_runtime.h>
#include <cuda_fp16.h>
#include <cstdint>

#define BATCH 8
#define NSEQ  2048
#define DIM   512
#define ROWS  (BATCH * NSEQ)   // 16384

// ---- mma.sync GEMM tiling ----
#define BM 128
#define BN 128
#define BK 32
#define NTHREADS 128
#define ROWB 80                         // smem row stride (bytes): conflict-free, 16B aligned
#define A_SM (BM * ROWB)                // 10240
#define B_SM (BN * ROWB)                // 10240
#define STAGE_SM (A_SM + B_SM)          // 20480
#define NSTAGE 4
#define SMEM_TOTAL (NSTAGE * STAGE_SM)  // 81920

#define XSZ (ROWS * DIM)
#define WSZ (DIM * DIM)
#define SSZ ((size_t)BATCH * NSEQ * NSEQ)

// ---------------------------------------------------------------------------
// Scratch (allocation-free rule: __device__ globals)
// ---------------------------------------------------------------------------
__device__ __half g_xh[2][XSZ];
__device__ __half g_wqh[2][WSZ];
__device__ __half g_wkh[2][WSZ];
__device__ __half g_wvh[2][WSZ];
__device__ __half g_qh[2][XSZ];
__device__ __half g_kh[2][XSZ];
__device__ float  g_v[XSZ];
__device__ __half g_vth[2][(size_t)BATCH * DIM * NSEQ];
__device__ float  g_s[SSZ];
__device__ __half g_ph[2][SSZ];

// ---------------------------------------------------------------------------
// PTX helpers
// ---------------------------------------------------------------------------
static __device__ __forceinline__ uint32_t smem_u32(const void* p) {
    uint32_t a;
    asm("{ .reg .u64 t; cvta.to.shared.u64 t, %1; cvt.u32.u64 %0, t; }" : "=r"(a) : "l"(p));
    return a;
}
static __device__ __forceinline__ void cp16(uint32_t saddr, const void* g) {
    asm volatile("cp.async.cg.shared.global [%0], [%1], 16;" :: "r"(saddr), "l"(g));
}
static __device__ __forceinline__ void cp_commit() {
    asm volatile("cp.async.commit_group;" ::: "memory");
}
static __device__ __forceinline__ void cp_wait0() {
    asm volatile("cp.async.wait_group 0;" ::: "memory");
}
static __device__ __forceinline__ void cp_wait1() {
    asm volatile("cp.async.wait_group 1;" ::: "memory");
}
static __device__ __forceinline__ void cp_wait2() {
    asm volatile("cp.async.wait_group 2;" ::: "memory");
}
#define LDSM4(R0, R1, R2, R3, addr) \
    asm volatile("ldmatrix.sync.aligned.m8n8.x4.shared.b16 {%0,%1,%2,%3}, [%4];" \
                 : "=r"(R0), "=r"(R1), "=r"(R2), "=r"(R3) : "r"(addr))
#define MMA16816(c0, c1, c2, c3, a0, a1, a2, a3, b0, b1) \
    asm volatile("mma.sync.aligned.m16n8k16.row.col.f32.f16.f16.f32 " \
                 "{%0,%1,%2,%3}, {%4,%5,%6,%7}, {%8,%9}, {%0,%1,%2,%3};" \
                 : "+f"(c0), "+f"(c1), "+f"(c2), "+f"(c3) \
                 : "r"(a0), "r"(a1), "r"(a2), "r"(a3), "r"(b0), "r"(b1))

// ---------------------------------------------------------------------------
// Elementwise 2-way fp16 split
// ---------------------------------------------------------------------------
__global__ void split2_kernel(const float* __restrict__ in,
                              __half* __restrict__ o1,
                              __half* __restrict__ o2, int n4)
{
    int i = blockIdx.x * blockDim.x + threadIdx.x;
    if (i >= n4) return;
    float4 v = ((const float4*)in)[i];
    float val[4] = {v.x, v.y, v.z, v.w};
    __half h1[4], h2[4];
#pragma unroll
    for (int j = 0; j < 4; j++) {
        h1[j] = __float2half_rn(val[j]);
        h2[j] = __float2half_rn(val[j] - __half2float(h1[j]));
    }
    ((__half2*)o1)[2 * i]     = __halves2half2(h1[0], h1[1]);
    ((__half2*)o1)[2 * i + 1] = __halves2half2(h1[2], h1[3]);
    ((__half2*)o2)[2 * i]     = __halves2half2(h2[0], h2[1]);
    ((__half2*)o2)[2 * i + 1] = __halves2half2(h2[2], h2[3]);
}

// ---------------------------------------------------------------------------
// V transpose + 2-way fp16 split: V[b][m][e] (fp32) -> vth[b][e][m]
// ---------------------------------------------------------------------------
__global__ void transpose_split2_kernel()
{
    __shared__ float tile[32][33];
    int b = blockIdx.z;
    int m0 = blockIdx.x * 32, e0 = blockIdx.y * 32;
    int tx = threadIdx.x, ty = threadIdx.y;
#pragma unroll
    for (int j = 0; j < 4; j++) {
        int m = m0 + ty + j * 8;
        tile[ty + j * 8][tx] = g_v[((size_t)(b * NSEQ + m)) * DIM + e0 + tx];
    }
    __syncthreads();
#pragma unroll
    for (int j = 0; j < 4; j++) {
        int e = e0 + ty + j * 8;
        float val = tile[tx][ty + j * 8];
        __half h1 = __float2half_rn(val);
        __half h2 = __float2half_rn(val - __half2float(h1));
        size_t idx = ((size_t)b * DIM + e) * NSEQ + m0 + tx;
        g_vth[0][idx] = h1;
        g_vth[1][idx] = h2;
    }
}

// ---------------------------------------------------------------------------
// Softmax over rows of S; writes 2-way fp16 split P
// ---------------------------------------------------------------------------
__global__ __launch_bounds__(256) void softmax_kernel()
{
    __shared__ float red[8];
    const float* S = g_s + (size_t)blockIdx.x * NSEQ;
    const int tid = threadIdx.x, lane = tid & 31, wid = tid >> 5;

    float4 v0 = *(const float4*)(S + tid * 8);
    float4 v1 = *(const float4*)(S + tid * 8 + 4);
    float e[8] = {v0.x, v0.y, v0.z, v0.w, v1.x, v1.y, v1.z, v1.w};

    float m = e[0];
#pragma unroll
    for (int i = 1; i < 8; i++) m = fmaxf(m, e[i]);
#pragma unroll
    for (int off = 16; off > 0; off >>= 1) m = fmaxf(m, __shfl_xor_sync(~0u, m, off));
    if (lane == 0) red[wid] = m;
    __syncthreads();
    float bm = red[0];
#pragma unroll
    for (int i = 1; i < 8; i++) bm = fmaxf(bm, red[i]);
    __syncthreads();

    float s = 0.f;
#pragma unroll
    for (int i = 0; i < 8; i++) { e[i] = __expf(e[i] - bm); s += e[i]; }
#pragma unroll
    for (int off = 16; off > 0; off >>= 1) s += __shfl_xor_sync(~0u, s, off);
    if (lane == 0) red[wid] = s;
    __syncthreads();
    float bs = 0.f;
#pragma unroll
    for (int i = 0; i < 8; i++) bs += red[i];
    float inv = 1.0f / bs;

    size_t base = (size_t)blockIdx.x * NSEQ + tid * 8;
    __half h1[8], h2[8];
#pragma unroll
    for (int i = 0; i < 8; i++) {
        float p = e[i] * inv;
        h1[i] = __float2half_rn(p);
        h2[i] = __float2half_rn(p - __half2float(h1[i]));
    }
#pragma unroll
    for (int i = 0; i < 4; i++) {
        ((__half2*)(g_ph[0] + base))[i] = __halves2half2(h1[2 * i], h1[2 * i + 1]);
        ((__half2*)(g_ph[1] + base))[i] = __halves2half2(h2[2 * i], h2[2 * i + 1]);
    }
}

// ---------------------------------------------------------------------------
// GEMM core (device function): C[m,n] = sum_p sum_k A_p[m,k]*B_p[n,k] (+bias)
// MODE 0: fp32 out.  MODE 2: 2-way fp16 split out.
// 128 threads; warp grid 2(m) x 2(n); warp tile 64x64; 4-stage cp.async.
// ---------------------------------------------------------------------------
template <int MODE>
static __device__ __forceinline__ void gemm_core(
    const __half* const* Aps, const __half* const* Bps,
    long long batchA, long long batchB, long long batchC,
    int npairs, int K, int lda, int ldb, int ldc,
    float* Cf, __half* C1, __half* C2, const float* bias,
    int nt, int mt, int bz, char* smem)
{
    const int tid  = threadIdx.x;
    const int wid  = tid >> 5;
    const int lane = tid & 31;

    const int m_base = (wid & 1) * 64;
    const int n_base = (wid >> 1) * 64;

    const uint32_t s0 = smem_u32(smem);

    const int KCH = K / BK;
    const int NIT = npairs * KCH;

    float acc[4][8][4];
#pragma unroll
    for (int i = 0; i < 4; i++)
#pragma unroll
        for (int j = 0; j < 8; j++)
#pragma unroll
            for (int r = 0; r < 4; r++) acc[i][j][r] = 0.f;

    const int lrow0 = tid >> 2;          // 0..31
    const int lc16  = tid & 3;           // 16B chunk within 64B row

    auto load_stage = [&](int it, int s) {
        int p = it / KCH, k0 = (it % KCH) * BK;
        const __half* Ab = Aps[p] + (size_t)bz * batchA + k0;
        const __half* Bb = Bps[p] + (size_t)bz * batchB + k0;
        uint32_t dA = s0 + s * STAGE_SM;
        uint32_t dB = dA + A_SM;
#pragma unroll
        for (int h = 0; h < 4; h++) {    // A: 128 rows
            int r = lrow0 + h * 32;
            cp16(dA + r * ROWB + lc16 * 16,
                 Ab + (size_t)(mt * BM + r) * lda + lc16 * 8);
        }
#pragma unroll
        for (int h = 0; h < 4; h++) {    // B: 128 rows
            int r = lrow0 + h * 32;
            cp16(dB + r * ROWB + lc16 * 16,
                 Bb + (size_t)(nt * BN + r) * ldb + lc16 * 8);
        }
        cp_commit();
    };

    load_stage(0, 0);
    if (NIT > 1) load_stage(1, 1);
    if (NIT > 2) load_stage(2, 2);

    for (int it = 0; it < NIT; it++) {
        if (it + 2 < NIT)      cp_wait2();
        else if (it + 1 < NIT) cp_wait1();
        else                   cp_wait0();
        __syncthreads();
        if (it + 3 < NIT) load_stage(it + 3, (it + 3) & 3);

        uint32_t bA = s0 + (it & 3) * STAGE_SM;
        uint32_t bB = bA + A_SM;
#pragma unroll
        for (int ks = 0; ks < 2; ks++) {
            uint32_t a[4][4];
#pragma unroll
            for (int mi = 0; mi < 4; mi++) {
                int row = m_base + mi * 16 + (lane & 15);
                int kc  = ks * 16 + (lane >> 4) * 8;
                LDSM4(a[mi][0], a[mi][1], a[mi][2], a[mi][3],
                      bA + row * ROWB + kc * 2);
            }
            uint32_t b[8][2];
#pragma unroll
            for (int j2 = 0; j2 < 4; j2++) {
                int grp = lane >> 3;
                int row = n_base + j2 * 16 + ((grp >> 1) * 8) + (lane & 7);
                int kc  = ks * 16 + (grp & 1) * 8;
                uint32_t r0, r1, r2, r3;
                LDSM4(r0, r1, r2, r3, bB + row * ROWB + kc * 2);
                b[2 * j2][0] = r0; b[2 * j2][1] = r1;
                b[2 * j2 + 1][0] = r2; b[2 * j2 + 1][1] = r3;
            }
#pragma unroll
            for (int mi = 0; mi < 4; mi++)
#pragma unroll
                for (int nj = 0; nj < 8; nj++)
                    MMA16816(acc[mi][nj][0], acc[mi][nj][1], acc[mi][nj][2], acc[mi][nj][3],
                             a[mi][0], a[mi][1], a[mi][2], a[mi][3],
                             b[nj][0], b[nj][1]);
        }
    }

    const int r0l = lane >> 2;
    const int c0l = (lane & 3) * 2;
#pragma unroll
    for (int mi = 0; mi < 4; mi++) {
#pragma unroll
        for (int half = 0; half < 2; half++) {
            int grow = mt * BM + m_base + mi * 16 + r0l + half * 8;
#pragma unroll
            for (int nj = 0; nj < 8; nj++) {
                int gcol = nt * BN + n_base + nj * 8 + c0l;
                float v0 = acc[mi][nj][2 * half];
                float v1 = acc[mi][nj][2 * half + 1];
                if (bias) { v0 += bias[gcol]; v1 += bias[gcol + 1]; }
                if (MODE == 0) {
                    float* C = Cf + (size_t)bz * batchC + (size_t)grow * ldc + gcol;
                    *(float2*)C = make_float2(v0, v1);
                } else {
                    size_t off = (size_t)grow * ldc + gcol;
                    __half a1 = __float2half_rn(v0);
                    __half a2 = __float2half_rn(v0 - __half2float(a1));
                    __half b1 = __float2half_rn(v1);
                    __half b2 = __float2half_rn(v1 - __half2float(b1));
                    *(__half2*)(C1 + off) = __halves2half2(a1, b1);
                    *(__half2*)(C2 + off) = __halves2half2(a2, b2);
                }
            }
        }
    }
}

// ---------------------------------------------------------------------------
// Generic batched GEMM kernel (scores / PV / single projections)
// ---------------------------------------------------------------------------
struct GemmArgs {
    const __half* A[3];
    const __half* B[3];
    long long batchA, batchB, batchC;
    int npairs, K, lda, ldb, ldc;
    float* Cf;
    __half *C1, *C2;
    const float* bias;
};

template <int MODE>
__global__ __launch_bounds__(NTHREADS)
void gemm_kernel(GemmArgs ga)
{
    extern __shared__ __align__(16) char smem[];
    gemm_core<MODE>(ga.A, ga.B, ga.batchA, ga.batchB, ga.batchC,
                    ga.npairs, ga.K, ga.lda, ga.ldb, ga.ldc,
                    ga.Cf, ga.C1, ga.C2, ga.bias,
                    blockIdx.x, blockIdx.y, blockIdx.z, smem);
}

// ---------------------------------------------------------------------------
// Merged QKV projection: grid.z = 0(Q) / 1(K) / 2(V)
// ---------------------------------------------------------------------------
struct ProjArgs {
    const __half* A[3];
    const __half* Bq[3];
    const __half* Bk[3];
    const __half* Bv[3];
    const float *bq, *bk, *bv;
    __half *q1, *q2, *k1, *k2;
    float* vout;
};

__global__ __launch_bounds__(NTHREADS)
void proj_kernel(ProjArgs pa)
{
    extern __shared__ __align__(16) char smem[];
    int z = blockIdx.z;
    if (z == 0) {
        gemm_core<2>(pa.A, pa.Bq, 0, 0, 0, 3, DIM, DIM, DIM, DIM,
                     nullptr, pa.q1, pa.q2, pa.bq,
                     blockIdx.x, blockIdx.y, 0, smem);
    } else if (z == 1) {
        gemm_core<2>(pa.A, pa.Bk, 0, 0, 0, 3, DIM, DIM, DIM, DIM,
                     nullptr, pa.k1, pa.k2, pa.bk,
                     blockIdx.x, blockIdx.y, 0, smem);
    } else {
        gemm_core<0>(pa.A, pa.Bv, 0, 0, 0, 3, DIM, DIM, DIM, DIM,
                     pa.vout, nullptr, nullptr, pa.bv,
                     blockIdx.x, blockIdx.y, 0, smem);
    }
}

// ---------------------------------------------------------------------------
extern "C" void kernel_launch(void* const* d_in, const int* in_sizes, int n_in,
                              void* d_out, int out_size)
{
    const float* x  = (const float*)d_in[0];
    const float* Wq = (const float*)d_in[1];
    const float* bq = (const float*)d_in[2];
    const float* Wk = (const float*)d_in[3];
    const float* bk = (const float*)d_in[4];
    const float* Wv = (const float*)d_in[5];
    const float* bv = (const float*)d_in[6];
    float* out = (float*)d_out;

    void* p;
    cudaGetSymbolAddress(&p, g_xh);  __half* xh = (__half*)p;
    cudaGetSymbolAddress(&p, g_wqh); __half* wqh = (__half*)p;
    cudaGetSymbolAddress(&p, g_wkh); __half* wkh = (__half*)p;
    cudaGetSymbolAddress(&p, g_wvh); __half* wvh = (__half*)p;
    cudaGetSymbolAddress(&p, g_qh);  __half* qh = (__half*)p;
    cudaGetSymbolAddress(&p, g_kh);  __half* kh = (__half*)p;
    cudaGetSymbolAddress(&p, g_v);   float* vptr = (float*)p;
    cudaGetSymbolAddress(&p, g_vth); __half* vth = (__half*)p;
    cudaGetSymbolAddress(&p, g_s);   float* sptr = (float*)p;
    cudaGetSymbolAddress(&p, g_ph);  __half* ph = (__half*)p;

    static bool attr_done = false;
    if (!attr_done) {
        cudaFuncSetAttribute((const void*)gemm_kernel<0>,
                             cudaFuncAttributeMaxDynamicSharedMemorySize, SMEM_TOTAL);
        cudaFuncSetAttribute((const void*)gemm_kernel<2>,
                             cudaFuncAttributeMaxDynamicSharedMemorySize, SMEM_TOTAL);
        cudaFuncSetAttribute((const void*)proj_kernel,
                             cudaFuncAttributeMaxDynamicSharedMemorySize, SMEM_TOTAL);
        attr_done = true;
    }

    // 1) 2-way fp16 splits of x and weights
    split2_kernel<<<(XSZ / 4 + 255) / 256, 256>>>(x,  xh,  xh + XSZ,  XSZ / 4);
    split2_kernel<<<(WSZ / 4 + 255) / 256, 256>>>(Wq, wqh, wqh + WSZ, WSZ / 4);
    split2_kernel<<<(WSZ / 4 + 255) / 256, 256>>>(Wk, wkh, wkh + WSZ, WSZ / 4);
    split2_kernel<<<(WSZ / 4 + 255) / 256, 256>>>(Wv, wvh, wvh + WSZ, WSZ / 4);

    const int Pa[3] = {0, 0, 1}, Pb[3] = {0, 1, 0};  // hi*hi, hi*lo, lo*hi

    // 2) merged Q/K/V projections
    {
        ProjArgs pa = {};
        for (int i = 0; i < 3; i++) {
            pa.A[i]  = xh  + (size_t)Pa[i] * XSZ;
            pa.Bq[i] = wqh + (size_t)Pb[i] * WSZ;
            pa.Bk[i] = wkh + (size_t)Pb[i] * WSZ;
            pa.Bv[i] = wvh + (size_t)Pb[i] * WSZ;
        }
        pa.bq = bq; pa.bk = bk; pa.bv = bv;
        pa.q1 = qh; pa.q2 = qh + XSZ;
        pa.k1 = kh; pa.k2 = kh + XSZ;
        pa.vout = vptr;
        proj_kernel<<<dim3(DIM / BN, ROWS / BM, 3), NTHREADS, SMEM_TOTAL>>>(pa);
    }
    // 3) V transpose + 2-split fp16
    transpose_split2_kernel<<<dim3(NSEQ / 32, DIM / 32, BATCH), dim3(32, 8)>>>();

    // 4) scores S = Q K^T (3 pairs, fp32)
    {
        GemmArgs ga = {};
        for (int i = 0; i < 3; i++) { ga.A[i] = qh + (size_t)Pa[i] * XSZ; ga.B[i] = kh + (size_t)Pb[i] * XSZ; }
        ga.batchA = ga.batchB = (long long)NSEQ * DIM;
        ga.batchC = (long long)NSEQ * NSEQ;
        ga.npairs = 3; ga.K = DIM; ga.lda = DIM; ga.ldb = DIM; ga.ldc = NSEQ;
        ga.Cf = sptr; ga.bias = nullptr;
        gemm_kernel<0><<<dim3(NSEQ / BN, NSEQ / BM, BATCH), NTHREADS, SMEM_TOTAL>>>(ga);
    }
    // 5) softmax -> 2-split fp16 P
    softmax_kernel<<<BATCH * NSEQ, 256>>>();

    // 6) O = P V (3 pairs, fp32)
    {
        GemmArgs ga = {};
        for (int i = 0; i < 3; i++) {
            ga.A[i] = ph + (size_t)Pa[i] * (size_t)SSZ;
            ga.B[i] = vth + (size_t)Pb[i] * ((size_t)BATCH * DIM * NSEQ);
        }
        ga.batchA = (long long)NSEQ * NSEQ;
        ga.batchB = (long long)DIM * NSEQ;
        ga.batchC = (long long)NSEQ * DIM;
        ga.npairs = 3; ga.K = NSEQ; ga.lda = NSEQ; ga.ldb = NSEQ; ga.ldc = DIM;
        ga.Cf = out; ga.bias = nullptr;
        gemm_kernel<0><<<dim3(DIM / BN, NSEQ / BM, BATCH), NTHREADS, SMEM_TOTAL>>>(ga);
    }
}

// round 15
// speedup vs baseline: 2.2976x; 1.0143x over previous
#include <cuda_runtime.h>
#include <cuda_fp16.h>
#include <cstdint>

#define BATCH 8
#define NSEQ  2048
#define DIM   512
#define ROWS  (BATCH * NSEQ)   // 16384

// ---- mma.sync GEMM tiling ----
#define BM 128
#define BN 128
#define BK 64
#define NTHREADS 128
#define ROWB 144                        // smem row stride (bytes): 128+16, conflict-free
#define A_SM (BM * ROWB)                // 18432
#define B_SM (BN * ROWB)                // 18432
#define STAGE_SM (A_SM + B_SM)          // 36864
#define NSTAGE 3
#define SMEM_TOTAL (NSTAGE * STAGE_SM)  // 110592  (2 CTAs/SM: 221184 < 228KB)

#define XSZ (ROWS * DIM)
#define WSZ (DIM * DIM)
#define SSZ ((size_t)BATCH * NSEQ * NSEQ)

// ---------------------------------------------------------------------------
// Scratch (allocation-free rule: __device__ globals)
// ---------------------------------------------------------------------------
__device__ __half g_xh[2][XSZ];
__device__ __half g_wqh[2][WSZ];
__device__ __half g_wkh[2][WSZ];
__device__ __half g_wvh[2][WSZ];
__device__ __half g_qh[2][XSZ];
__device__ __half g_kh[2][XSZ];
__device__ float  g_v[XSZ];
__device__ __half g_vth[2][(size_t)BATCH * DIM * NSEQ];
__device__ float  g_s[SSZ];
__device__ __half g_ph[2][SSZ];

// ---------------------------------------------------------------------------
// PTX helpers
// ---------------------------------------------------------------------------
static __device__ __forceinline__ uint32_t smem_u32(const void* p) {
    uint32_t a;
    asm("{ .reg .u64 t; cvta.to.shared.u64 t, %1; cvt.u32.u64 %0, t; }" : "=r"(a) : "l"(p));
    return a;
}
static __device__ __forceinline__ void cp16(uint32_t saddr, const void* g) {
    asm volatile("cp.async.cg.shared.global [%0], [%1], 16;" :: "r"(saddr), "l"(g));
}
static __device__ __forceinline__ void cp_commit() {
    asm volatile("cp.async.commit_group;" ::: "memory");
}
static __device__ __forceinline__ void cp_wait0() {
    asm volatile("cp.async.wait_group 0;" ::: "memory");
}
static __device__ __forceinline__ void cp_wait1() {
    asm volatile("cp.async.wait_group 1;" ::: "memory");
}
#define LDSM4(R0, R1, R2, R3, addr) \
    asm volatile("ldmatrix.sync.aligned.m8n8.x4.shared.b16 {%0,%1,%2,%3}, [%4];" \
                 : "=r"(R0), "=r"(R1), "=r"(R2), "=r"(R3) : "r"(addr))
#define MMA16816(c0, c1, c2, c3, a0, a1, a2, a3, b0, b1) \
    asm volatile("mma.sync.aligned.m16n8k16.row.col.f32.f16.f16.f32 " \
                 "{%0,%1,%2,%3}, {%4,%5,%6,%7}, {%8,%9}, {%0,%1,%2,%3};" \
                 : "+f"(c0), "+f"(c1), "+f"(c2), "+f"(c3) \
                 : "r"(a0), "r"(a1), "r"(a2), "r"(a3), "r"(b0), "r"(b1))

// ---------------------------------------------------------------------------
// Elementwise 2-way fp16 split
// ---------------------------------------------------------------------------
__global__ void split2_kernel(const float* __restrict__ in,
                              __half* __restrict__ o1,
                              __half* __restrict__ o2, int n4)
{
    int i = blockIdx.x * blockDim.x + threadIdx.x;
    if (i >= n4) return;
    float4 v = ((const float4*)in)[i];
    float val[4] = {v.x, v.y, v.z, v.w};
    __half h1[4], h2[4];
#pragma unroll
    for (int j = 0; j < 4; j++) {
        h1[j] = __float2half_rn(val[j]);
        h2[j] = __float2half_rn(val[j] - __half2float(h1[j]));
    }
    ((__half2*)o1)[2 * i]     = __halves2half2(h1[0], h1[1]);
    ((__half2*)o1)[2 * i + 1] = __halves2half2(h1[2], h1[3]);
    ((__half2*)o2)[2 * i]     = __halves2half2(h2[0], h2[1]);
    ((__half2*)o2)[2 * i + 1] = __halves2half2(h2[2], h2[3]);
}

// ---------------------------------------------------------------------------
// V transpose + 2-way fp16 split: V[b][m][e] (fp32) -> vth[b][e][m]
// ---------------------------------------------------------------------------
__global__ void transpose_split2_kernel()
{
    __shared__ float tile[32][33];
    int b = blockIdx.z;
    int m0 = blockIdx.x * 32, e0 = blockIdx.y * 32;
    int tx = threadIdx.x, ty = threadIdx.y;
#pragma unroll
    for (int j = 0; j < 4; j++) {
        int m = m0 + ty + j * 8;
        tile[ty + j * 8][tx] = g_v[((size_t)(b * NSEQ + m)) * DIM + e0 + tx];
    }
    __syncthreads();
#pragma unroll
    for (int j = 0; j < 4; j++) {
        int e = e0 + ty + j * 8;
        float val = tile[tx][ty + j * 8];
        __half h1 = __float2half_rn(val);
        __half h2 = __float2half_rn(val - __half2float(h1));
        size_t idx = ((size_t)b * DIM + e) * NSEQ + m0 + tx;
        g_vth[0][idx] = h1;
        g_vth[1][idx] = h2;
    }
}

// ---------------------------------------------------------------------------
// Softmax over rows of S; writes 2-way fp16 split P
// ---------------------------------------------------------------------------
__global__ __launch_bounds__(256) void softmax_kernel()
{
    __shared__ float red[8];
    const float* S = g_s + (size_t)blockIdx.x * NSEQ;
    const int tid = threadIdx.x, lane = tid & 31, wid = tid >> 5;

    float4 v0 = *(const float4*)(S + tid * 8);
    float4 v1 = *(const float4*)(S + tid * 8 + 4);
    float e[8] = {v0.x, v0.y, v0.z, v0.w, v1.x, v1.y, v1.z, v1.w};

    float m = e[0];
#pragma unroll
    for (int i = 1; i < 8; i++) m = fmaxf(m, e[i]);
#pragma unroll
    for (int off = 16; off > 0; off >>= 1) m = fmaxf(m, __shfl_xor_sync(~0u, m, off));
    if (lane == 0) red[wid] = m;
    __syncthreads();
    float bm = red[0];
#pragma unroll
    for (int i = 1; i < 8; i++) bm = fmaxf(bm, red[i]);
    __syncthreads();

    float s = 0.f;
#pragma unroll
    for (int i = 0; i < 8; i++) { e[i] = __expf(e[i] - bm); s += e[i]; }
#pragma unroll
    for (int off = 16; off > 0; off >>= 1) s += __shfl_xor_sync(~0u, s, off);
    if (lane == 0) red[wid] = s;
    __syncthreads();
    float bs = 0.f;
#pragma unroll
    for (int i = 0; i < 8; i++) bs += red[i];
    float inv = 1.0f / bs;

    size_t base = (size_t)blockIdx.x * NSEQ + tid * 8;
    __half h1[8], h2[8];
#pragma unroll
    for (int i = 0; i < 8; i++) {
        float p = e[i] * inv;
        h1[i] = __float2half_rn(p);
        h2[i] = __float2half_rn(p - __half2float(h1[i]));
    }
#pragma unroll
    for (int i = 0; i < 4; i++) {
        ((__half2*)(g_ph[0] + base))[i] = __halves2half2(h1[2 * i], h1[2 * i + 1]);
        ((__half2*)(g_ph[1] + base))[i] = __halves2half2(h2[2 * i], h2[2 * i + 1]);
    }
}

// ---------------------------------------------------------------------------
// GEMM core (device function): C[m,n] = sum_p sum_k A_p[m,k]*B_p[n,k] (+bias)
// MODE 0: fp32 out.  MODE 2: 2-way fp16 split out.
// 128 threads; warp grid 2(m) x 2(n); warp tile 64x64; BK=64; 3-stage cp.async.
// ---------------------------------------------------------------------------
template <int MODE>
static __device__ __forceinline__ void gemm_core(
    const __half* const* Aps, const __half* const* Bps,
    long long batchA, long long batchB, long long batchC,
    int npairs, int K, int lda, int ldb, int ldc,
    float* Cf, __half* C1, __half* C2, const float* bias,
    int nt, int mt, int bz, char* smem)
{
    const int tid  = threadIdx.x;
    const int wid  = tid >> 5;
    const int lane = tid & 31;

    const int m_base = (wid & 1) * 64;
    const int n_base = (wid >> 1) * 64;

    const uint32_t s0 = smem_u32(smem);

    const int KCH = K / BK;
    const int NIT = npairs * KCH;

    float acc[4][8][4];
#pragma unroll
    for (int i = 0; i < 4; i++)
#pragma unroll
        for (int j = 0; j < 8; j++)
#pragma unroll
            for (int r = 0; r < 4; r++) acc[i][j][r] = 0.f;

    const int lrow0 = tid >> 3;          // 0..15
    const int lc16  = tid & 7;           // 16B chunk within 128B row

    auto load_stage = [&](int it, int s) {
        int p = it / KCH, k0 = (it % KCH) * BK;
        const __half* Ab = Aps[p] + (size_t)bz * batchA + k0;
        const __half* Bb = Bps[p] + (size_t)bz * batchB + k0;
        uint32_t dA = s0 + s * STAGE_SM;
        uint32_t dB = dA + A_SM;
#pragma unroll
        for (int h = 0; h < 8; h++) {    // A: 128 rows x 128B
            int r = lrow0 + h * 16;
            cp16(dA + r * ROWB + lc16 * 16,
                 Ab + (size_t)(mt * BM + r) * lda + lc16 * 8);
        }
#pragma unroll
        for (int h = 0; h < 8; h++) {    // B: 128 rows x 128B
            int r = lrow0 + h * 16;
            cp16(dB + r * ROWB + lc16 * 16,
                 Bb + (size_t)(nt * BN + r) * ldb + lc16 * 8);
        }
        cp_commit();
    };

    load_stage(0, 0);
    if (NIT > 1) load_stage(1, 1);

    int st = 0;                           // stage of iteration it
    for (int it = 0; it < NIT; it++) {
        if (it + 1 < NIT) cp_wait1(); else cp_wait0();
        __syncthreads();
        if (it + 2 < NIT) {
            int s2 = st + 2; if (s2 >= NSTAGE) s2 -= NSTAGE;
            load_stage(it + 2, s2);
        }

        uint32_t bA = s0 + st * STAGE_SM;
        uint32_t bB = bA + A_SM;
#pragma unroll
        for (int ks = 0; ks < 4; ks++) {
            uint32_t a[4][4];
#pragma unroll
            for (int mi = 0; mi < 4; mi++) {
                int row = m_base + mi * 16 + (lane & 15);
                int kc  = ks * 16 + (lane >> 4) * 8;
                LDSM4(a[mi][0], a[mi][1], a[mi][2], a[mi][3],
                      bA + row * ROWB + kc * 2);
            }
            uint32_t b[8][2];
#pragma unroll
            for (int j2 = 0; j2 < 4; j2++) {
                int grp = lane >> 3;
                int row = n_base + j2 * 16 + ((grp >> 1) * 8) + (lane & 7);
                int kc  = ks * 16 + (grp & 1) * 8;
                uint32_t r0, r1, r2, r3;
                LDSM4(r0, r1, r2, r3, bB + row * ROWB + kc * 2);
                b[2 * j2][0] = r0; b[2 * j2][1] = r1;
                b[2 * j2 + 1][0] = r2; b[2 * j2 + 1][1] = r3;
            }
#pragma unroll
            for (int mi = 0; mi < 4; mi++)
#pragma unroll
                for (int nj = 0; nj < 8; nj++)
                    MMA16816(acc[mi][nj][0], acc[mi][nj][1], acc[mi][nj][2], acc[mi][nj][3],
                             a[mi][0], a[mi][1], a[mi][2], a[mi][3],
                             b[nj][0], b[nj][1]);
        }
        if (++st >= NSTAGE) st = 0;
    }

    const int r0l = lane >> 2;
    const int c0l = (lane & 3) * 2;
#pragma unroll
    for (int mi = 0; mi < 4; mi++) {
#pragma unroll
        for (int half = 0; half < 2; half++) {
            int grow = mt * BM + m_base + mi * 16 + r0l + half * 8;
#pragma unroll
            for (int nj = 0; nj < 8; nj++) {
                int gcol = nt * BN + n_base + nj * 8 + c0l;
                float v0 = acc[mi][nj][2 * half];
                float v1 = acc[mi][nj][2 * half + 1];
                if (bias) { v0 += bias[gcol]; v1 += bias[gcol + 1]; }
                if (MODE == 0) {
                    float* C = Cf + (size_t)bz * batchC + (size_t)grow * ldc + gcol;
                    *(float2*)C = make_float2(v0, v1);
                } else {
                    size_t off = (size_t)grow * ldc + gcol;
                    __half a1 = __float2half_rn(v0);
                    __half a2 = __float2half_rn(v0 - __half2float(a1));
                    __half b1 = __float2half_rn(v1);
                    __half b2 = __float2half_rn(v1 - __half2float(b1));
                    *(__half2*)(C1 + off) = __halves2half2(a1, b1);
                    *(__half2*)(C2 + off) = __halves2half2(a2, b2);
                }
            }
        }
    }
}

// ---------------------------------------------------------------------------
// Generic batched GEMM kernel (scores / PV)
// ---------------------------------------------------------------------------
struct GemmArgs {
    const __half* A[3];
    const __half* B[3];
    long long batchA, batchB, batchC;
    int npairs, K, lda, ldb, ldc;
    float* Cf;
    __half *C1, *C2;
    const float* bias;
};

template <int MODE>
__global__ __launch_bounds__(NTHREADS)
void gemm_kernel(GemmArgs ga)
{
    extern __shared__ __align__(16) char smem[];
    gemm_core<MODE>(ga.A, ga.B, ga.batchA, ga.batchB, ga.batchC,
                    ga.npairs, ga.K, ga.lda, ga.ldb, ga.ldc,
                    ga.Cf, ga.C1, ga.C2, ga.bias,
                    blockIdx.x, blockIdx.y, blockIdx.z, smem);
}

// ---------------------------------------------------------------------------
// Merged QKV projection: grid.z = 0(Q) / 1(K) / 2(V)
// ---------------------------------------------------------------------------
struct ProjArgs {
    const __half* A[3];
    const __half* Bq[3];
    const __half* Bk[3];
    const __half* Bv[3];
    const float *bq, *bk, *bv;
    __half *q1, *q2, *k1, *k2;
    float* vout;
};

__global__ __launch_bounds__(NTHREADS)
void proj_kernel(ProjArgs pa)
{
    extern __shared__ __align__(16) char smem[];
    int z = blockIdx.z;
    if (z == 0) {
        gemm_core<2>(pa.A, pa.Bq, 0, 0, 0, 3, DIM, DIM, DIM, DIM,
                     nullptr, pa.q1, pa.q2, pa.bq,
                     blockIdx.x, blockIdx.y, 0, smem);
    } else if (z == 1) {
        gemm_core<2>(pa.A, pa.Bk, 0, 0, 0, 3, DIM, DIM, DIM, DIM,
                     nullptr, pa.k1, pa.k2, pa.bk,
                     blockIdx.x, blockIdx.y, 0, smem);
    } else {
        gemm_core<0>(pa.A, pa.Bv, 0, 0, 0, 3, DIM, DIM, DIM, DIM,
                     pa.vout, nullptr, nullptr, pa.bv,
                     blockIdx.x, blockIdx.y, 0, smem);
    }
}

// ---------------------------------------------------------------------------
extern "C" void kernel_launch(void* const* d_in, const int* in_sizes, int n_in,
                              void* d_out, int out_size)
{
    const float* x  = (const float*)d_in[0];
    const float* Wq = (const float*)d_in[1];
    const float* bq = (const float*)d_in[2];
    const float* Wk = (const float*)d_in[3];
    const float* bk = (const float*)d_in[4];
    const float* Wv = (const float*)d_in[5];
    const float* bv = (const float*)d_in[6];
    float* out = (float*)d_out;

    void* p;
    cudaGetSymbolAddress(&p, g_xh);  __half* xh = (__half*)p;
    cudaGetSymbolAddress(&p, g_wqh); __half* wqh = (__half*)p;
    cudaGetSymbolAddress(&p, g_wkh); __half* wkh = (__half*)p;
    cudaGetSymbolAddress(&p, g_wvh); __half* wvh = (__half*)p;
    cudaGetSymbolAddress(&p, g_qh);  __half* qh = (__half*)p;
    cudaGetSymbolAddress(&p, g_kh);  __half* kh = (__half*)p;
    cudaGetSymbolAddress(&p, g_v);   float* vptr = (float*)p;
    cudaGetSymbolAddress(&p, g_vth); __half* vth = (__half*)p;
    cudaGetSymbolAddress(&p, g_s);   float* sptr = (float*)p;
    cudaGetSymbolAddress(&p, g_ph);  __half* ph = (__half*)p;

    static bool attr_done = false;
    if (!attr_done) {
        cudaFuncSetAttribute((const void*)gemm_kernel<0>,
                             cudaFuncAttributeMaxDynamicSharedMemorySize, SMEM_TOTAL);
        cudaFuncSetAttribute((const void*)gemm_kernel<2>,
                             cudaFuncAttributeMaxDynamicSharedMemorySize, SMEM_TOTAL);
        cudaFuncSetAttribute((const void*)proj_kernel,
                             cudaFuncAttributeMaxDynamicSharedMemorySize, SMEM_TOTAL);
        attr_done = true;
    }

    // 1) 2-way fp16 splits of x and weights
    split2_kernel<<<(XSZ / 4 + 255) / 256, 256>>>(x,  xh,  xh + XSZ,  XSZ / 4);
    split2_kernel<<<(WSZ / 4 + 255) / 256, 256>>>(Wq, wqh, wqh + WSZ, WSZ / 4);
    split2_kernel<<<(WSZ / 4 + 255) / 256, 256>>>(Wk, wkh, wkh + WSZ, WSZ / 4);
    split2_kernel<<<(WSZ / 4 + 255) / 256, 256>>>(Wv, wvh, wvh + WSZ, WSZ / 4);

    const int Pa[3] = {0, 0, 1}, Pb[3] = {0, 1, 0};  // hi*hi, hi*lo, lo*hi

    // 2) merged Q/K/V projections
    {
        ProjArgs pa = {};
        for (int i = 0; i < 3; i++) {
            pa.A[i]  = xh  + (size_t)Pa[i] * XSZ;
            pa.Bq[i] = wqh + (size_t)Pb[i] * WSZ;
            pa.Bk[i] = wkh + (size_t)Pb[i] * WSZ;
            pa.Bv[i] = wvh + (size_t)Pb[i] * WSZ;
        }
        pa.bq = bq; pa.bk = bk; pa.bv = bv;
        pa.q1 = qh; pa.q2 = qh + XSZ;
        pa.k1 = kh; pa.k2 = kh + XSZ;
        pa.vout = vptr;
        proj_kernel<<<dim3(DIM / BN, ROWS / BM, 3), NTHREADS, SMEM_TOTAL>>>(pa);
    }
    // 3) V transpose + 2-split fp16
    transpose_split2_kernel<<<dim3(NSEQ / 32, DIM / 32, BATCH), dim3(32, 8)>>>();

    // 4) scores S = Q K^T (3 pairs, fp32)
    {
        GemmArgs ga = {};
        for (int i = 0; i < 3; i++) { ga.A[i] = qh + (size_t)Pa[i] * XSZ; ga.B[i] = kh + (size_t)Pb[i] * XSZ; }
        ga.batchA = ga.batchB = (long long)NSEQ * DIM;
        ga.batchC = (long long)NSEQ * NSEQ;
        ga.npairs = 3; ga.K = DIM; ga.lda = DIM; ga.ldb = DIM; ga.ldc = NSEQ;
        ga.Cf = sptr; ga.bias = nullptr;
        gemm_kernel<0><<<dim3(NSEQ / BN, NSEQ / BM, BATCH), NTHREADS, SMEM_TOTAL>>>(ga);
    }
    // 5) softmax -> 2-split fp16 P
    softmax_kernel<<<BATCH * NSEQ, 256>>>();

    // 6) O = P V (3 pairs, fp32)
    {
        GemmArgs ga = {};
        for (int i = 0; i < 3; i++) {
            ga.A[i] = ph + (size_t)Pa[i] * (size_t)SSZ;
            ga.B[i] = vth + (size_t)Pb[i] * ((size_t)BATCH * DIM * NSEQ);
        }
        ga.batchA = (long long)NSEQ * NSEQ;
        ga.batchB = (long long)DIM * NSEQ;
        ga.batchC = (long long)NSEQ * DIM;
        ga.npairs = 3; ga.K = NSEQ; ga.lda = NSEQ; ga.ldb = NSEQ; ga.ldc = DIM;
        ga.Cf = out; ga.bias = nullptr;
        gemm_kernel<0><<<dim3(DIM / BN, NSEQ / BM, BATCH), NTHREADS, SMEM_TOTAL>>>(ga);
    }
}